// round 12
// baseline (speedup 1.0000x reference)
#include <cuda_runtime.h>
#include <cuda_fp16.h>
#include <math.h>

#define N_NODES 100000
#define N_EDGES 1600000
#define IN_C 64
#define HID_C 64
#define OUT_C 40
#define SCAN_BS 512
#define SCAN_NB ((N_NODES + SCAN_BS - 1) / SCAN_BS)   // 196

// Scratch (allocation-free rule: __device__ globals)
__device__ uint2 g_bufA[(size_t)N_NODES * (HID_C / 4)]; // fp16 messages (layers 1 & 3)
__device__ uint2 g_bufB[(size_t)N_NODES * (HID_C / 4)]; // fp16 messages (layer 2)
__device__ float g_dinv[N_NODES];
__device__ int   g_deg[N_NODES];
__device__ int   g_rowptr[N_NODES + 1];
__device__ int   g_cursor[N_NODES];
__device__ int   g_bsum[SCAN_NB];
__device__ int2  g_epair[N_EDGES];                 // {src, norm(bits)} binned by dst

// ---------------------------------------------------------------------------
// packed f32x2 helpers (Blackwell: 1 instr = 2 fp32 MACs)
// ---------------------------------------------------------------------------
__device__ __forceinline__ void fma2(unsigned long long& d, unsigned long long a,
                                     unsigned long long b) {
    asm("fma.rn.f32x2 %0, %1, %2, %0;" : "+l"(d) : "l"(a), "l"(b));
}
__device__ __forceinline__ unsigned long long bcast2(float x) {
    unsigned long long p;
    asm("mov.b64 %0, {%1, %1};" : "=l"(p) : "f"(x));
    return p;
}
__device__ __forceinline__ unsigned long long pair2(float lo, float hi) {
    unsigned long long p;
    asm("mov.b64 %0, {%1, %2};" : "=l"(p) : "f"(lo), "f"(hi));
    return p;
}
__device__ __forceinline__ void unpack2(unsigned long long p, float& lo, float& hi) {
    asm("mov.b64 {%0, %1}, %2;" : "=f"(lo), "=f"(hi) : "l"(p));
}

__device__ __forceinline__ float4 h4_to_f4(uint2 raw) {
    __half2 a = *reinterpret_cast<__half2*>(&raw.x);
    __half2 b = *reinterpret_cast<__half2*>(&raw.y);
    float2 fa = __half22float2(a);
    float2 fb = __half22float2(b);
    return make_float4(fa.x, fa.y, fb.x, fb.y);
}

// ---------------------------------------------------------------------------
// degree
// ---------------------------------------------------------------------------
__global__ void deg_kernel(const int* __restrict__ dst, int E) {
    int i = blockIdx.x * blockDim.x + threadIdx.x;
    if (i < E) atomicAdd(&g_deg[dst[i]], 1);
}

// ---------------------------------------------------------------------------
// CSR build: block-wise exclusive scan of deg -> rowptr (dinv fused here)
// ---------------------------------------------------------------------------
__global__ void scan_block_kernel(int N) {
    __shared__ int s[SCAN_BS];
    int i = blockIdx.x * SCAN_BS + threadIdx.x;
    int v = (i < N) ? g_deg[i] : 0;
    if (i < N) g_dinv[i] = rsqrtf((float)(v + 1));     // +1 self loop; always > 0
    s[threadIdx.x] = v;
    __syncthreads();
#pragma unroll
    for (int off = 1; off < SCAN_BS; off <<= 1) {
        int t = 0;
        if (threadIdx.x >= off) t = s[threadIdx.x - off];
        __syncthreads();
        if (threadIdx.x >= off) s[threadIdx.x] += t;
        __syncthreads();
    }
    if (i < N) g_rowptr[i] = s[threadIdx.x] - v;       // exclusive, block-local
    if (threadIdx.x == SCAN_BS - 1) g_bsum[blockIdx.x] = s[SCAN_BS - 1];
}

// add block offsets (each block redundantly scans the 196 block sums in smem)
__global__ void add_off_kernel(int N, int E) {
    __shared__ int s[256];
    int t = threadIdx.x;
    int v = (t < SCAN_NB) ? g_bsum[t] : 0;
    s[t] = v;
    __syncthreads();
#pragma unroll
    for (int off = 1; off < 256; off <<= 1) {
        int u = 0;
        if (t >= off) u = s[t - off];
        __syncthreads();
        if (t >= off) s[t] += u;
        __syncthreads();
    }
    int i = blockIdx.x * blockDim.x + threadIdx.x;
    if (i < N) {
        int b = i >> 9;
        int off = (b > 0) ? s[b - 1] : 0;          // exclusive prefix of bsum
        int r = g_rowptr[i] + off;
        g_rowptr[i] = r;
        g_cursor[i] = r;
    }
    if (i == 0) g_rowptr[N] = E;
}

__global__ void fill_kernel(const int* __restrict__ src, const int* __restrict__ dst, int E) {
    int e = blockIdx.x * blockDim.x + threadIdx.x;
    if (e >= E) return;
    int s = src[e], d = dst[e];
    float nrm = g_dinv[s] * g_dinv[d];
    int pos = atomicAdd(&g_cursor[d], 1);
    g_epair[pos] = make_int2(s, __float_as_int(nrm));
}

// ---------------------------------------------------------------------------
// dense transform, fp16 output (layer 1): fp32 f32x2 accumulate.
// 2 threads/row, interleaved chunks. Row = OUT/4 uint2.
// ---------------------------------------------------------------------------
template <int IN, int OUT, bool RELU>
__global__ void __launch_bounds__(256) gemmh_kernel(const float* __restrict__ X,
                                                    const float* __restrict__ W,
                                                    uint2* __restrict__ Yh, int N) {
    constexpr int NJ = OUT / 8;
    __shared__ __align__(16) float Ws[IN * OUT];
    for (int i = threadIdx.x; i < IN * OUT; i += blockDim.x) Ws[i] = W[i];
    __syncthreads();

    int half = threadIdx.x & 1;
    int r = blockIdx.x * 128 + (threadIdx.x >> 1);
    if (r >= N) return;

    unsigned long long acc[2 * NJ];
#pragma unroll
    for (int j = 0; j < 2 * NJ; j++) acc[j] = 0ull;

    const float4* xr = reinterpret_cast<const float4*>(X + (size_t)r * IN);
#pragma unroll 4
    for (int k4 = 0; k4 < IN / 4; k4++) {
        float4 xv = xr[k4];
        if (RELU) {
            xv.x = fmaxf(xv.x, 0.f); xv.y = fmaxf(xv.y, 0.f);
            xv.z = fmaxf(xv.z, 0.f); xv.w = fmaxf(xv.w, 0.f);
        }
        float xs[4] = {xv.x, xv.y, xv.z, xv.w};
#pragma unroll
        for (int kk = 0; kk < 4; kk++) {
            unsigned long long xx = bcast2(xs[kk]);
            const float4* wr = reinterpret_cast<const float4*>(Ws + (4 * k4 + kk) * OUT);
#pragma unroll
            for (int j = 0; j < NJ; j++) {
                float4 w = wr[2 * j + half];
                fma2(acc[2 * j],     xx, pair2(w.x, w.y));
                fma2(acc[2 * j + 1], xx, pair2(w.z, w.w));
            }
        }
    }
    uint2* yr = Yh + (size_t)r * (OUT / 4);
#pragma unroll
    for (int j = 0; j < NJ; j++) {
        float l0, h0, l1, h1;
        unpack2(acc[2 * j],     l0, h0);
        unpack2(acc[2 * j + 1], l1, h1);
        __half2 a = __floats2half2_rn(l0, h0);
        __half2 b = __floats2half2_rn(l1, h1);
        uint2 o;
        o.x = *reinterpret_cast<unsigned int*>(&a);
        o.y = *reinterpret_cast<unsigned int*>(&b);
        yr[2 * j + half] = o;
    }
}

// ---------------------------------------------------------------------------
// FUSED: aggregate (round-9 proven loop, 64-wide fp16 messages) -> relu(h) in
// smem -> per-row gemm (16 lanes x 4 cols, f32x2) -> fp16 messages out.
// Block = 256 threads = 16 rows x 16 lanes.
// ---------------------------------------------------------------------------
template <int OUTC>
__global__ void __launch_bounds__(256) fused_agg_gemm_kernel(
    const uint2* __restrict__ th, const float* __restrict__ b,
    const float* __restrict__ W, uint2* __restrict__ Yh, int N) {
    constexpr int OC4 = OUTC / 4;
    __shared__ float xs[16][68];                     // relu(h) tile, padded
    __shared__ __align__(16) float Ws[HID_C * OUTC]; // weights

    int tid = threadIdx.x;
    // stage W (64 x OUTC floats)
    {
        const float4* Wg = reinterpret_cast<const float4*>(W);
        float4* Wst = reinterpret_cast<float4*>(Ws);
        for (int i = tid; i < 16 * OUTC; i += 256) Wst[i] = Wg[i];
    }

    int rloc = tid >> 4;
    int lane = tid & 15;
    int row  = blockIdx.x * 16 + rloc;
    bool rowok = (row < N);
    int rr = rowok ? row : 0;

    // ---- phase 1: aggregate (proven structure; all 16 lanes active) ----
    float4 acc = make_float4(0.f, 0.f, 0.f, 0.f);
    int beg = 0, end = 0;
    if (rowok) {
        beg = g_rowptr[rr];
        end = g_rowptr[rr + 1];
        float di = g_dinv[rr];
        float s2 = di * di;
        float4 t = h4_to_f4(__ldg(&th[(size_t)rr * 16 + lane]));
        float4 bb = reinterpret_cast<const float4*>(b)[lane];
        acc.x = bb.x + s2 * t.x; acc.y = bb.y + s2 * t.y;
        acc.z = bb.z + s2 * t.z; acc.w = bb.w + s2 * t.w;
    }

    int j = beg;
    for (; j + 3 < end; j += 4) {
        int2 p0 = __ldg(&g_epair[j]);
        int2 p1 = __ldg(&g_epair[j + 1]);
        int2 p2 = __ldg(&g_epair[j + 2]);
        int2 p3 = __ldg(&g_epair[j + 3]);
        float4 v0 = h4_to_f4(__ldg(&th[(size_t)p0.x * 16 + lane]));
        float4 v1 = h4_to_f4(__ldg(&th[(size_t)p1.x * 16 + lane]));
        float4 v2 = h4_to_f4(__ldg(&th[(size_t)p2.x * 16 + lane]));
        float4 v3 = h4_to_f4(__ldg(&th[(size_t)p3.x * 16 + lane]));
        float n0 = __int_as_float(p0.y), n1 = __int_as_float(p1.y);
        float n2 = __int_as_float(p2.y), n3 = __int_as_float(p3.y);
        acc.x += n0 * v0.x + n1 * v1.x + n2 * v2.x + n3 * v3.x;
        acc.y += n0 * v0.y + n1 * v1.y + n2 * v2.y + n3 * v3.y;
        acc.z += n0 * v0.z + n1 * v1.z + n2 * v2.z + n3 * v3.z;
        acc.w += n0 * v0.w + n1 * v1.w + n2 * v2.w + n3 * v3.w;
    }
    for (; j < end; j++) {
        int2 p0 = __ldg(&g_epair[j]);
        float4 v0 = h4_to_f4(__ldg(&th[(size_t)p0.x * 16 + lane]));
        float n0 = __int_as_float(p0.y);
        acc.x += n0 * v0.x; acc.y += n0 * v0.y;
        acc.z += n0 * v0.z; acc.w += n0 * v0.w;
    }

    // relu(h) -> smem tile
    float4 o = make_float4(fmaxf(acc.x, 0.f), fmaxf(acc.y, 0.f),
                           fmaxf(acc.z, 0.f), fmaxf(acc.w, 0.f));
    *reinterpret_cast<float4*>(&xs[rloc][4 * lane]) = o;   // safe even if !rowok
    __syncthreads();

    // ---- phase 2: per-row gemm, lane -> 4 output cols ----
    if (rowok && lane < OC4) {
        unsigned long long a0 = 0ull, a1 = 0ull;
        const float4* W4 = reinterpret_cast<const float4*>(Ws);
        const float* xrow = xs[rloc];
#pragma unroll 4
        for (int k4 = 0; k4 < 16; k4++) {
            float4 xq = *reinterpret_cast<const float4*>(&xrow[4 * k4]);
            float xk[4] = {xq.x, xq.y, xq.z, xq.w};
#pragma unroll
            for (int kk = 0; kk < 4; kk++) {
                unsigned long long xx = bcast2(xk[kk]);
                float4 w = W4[(4 * k4 + kk) * OC4 + lane];
                fma2(a0, xx, pair2(w.x, w.y));
                fma2(a1, xx, pair2(w.z, w.w));
            }
        }
        float l0, h0, l1, h1;
        unpack2(a0, l0, h0);
        unpack2(a1, l1, h1);
        __half2 ha = __floats2half2_rn(l0, h0);
        __half2 hb = __floats2half2_rn(l1, h1);
        uint2 om;
        om.x = *reinterpret_cast<unsigned int*>(&ha);
        om.y = *reinterpret_cast<unsigned int*>(&hb);
        Yh[(size_t)row * OC4 + lane] = om;
    }
}

// ---------------------------------------------------------------------------
// CSR aggregate over fp16 messages + fused log_softmax (layer 3, proven)
// ---------------------------------------------------------------------------
template <int C4>
__global__ void aggregateh_lsm_kernel(const uint2* __restrict__ th, const float* __restrict__ b,
                                      float* __restrict__ outp, int N) {
    int g    = blockIdx.x * 16 + (threadIdx.x >> 4);
    int lane = threadIdx.x & 15;
    bool rowok = (g < N);
    int row  = rowok ? g : 0;
    bool act = rowok && (lane < C4);

    const float4* b4 = reinterpret_cast<const float4*>(b);

    float4 acc = make_float4(0.f, 0.f, 0.f, 0.f);
    int beg = 0, end = 0;
    if (rowok) {
        beg = g_rowptr[row];
        end = g_rowptr[row + 1];
    }
    if (act) {
        float di = g_dinv[row];
        float s2 = di * di;
        float4 t = h4_to_f4(__ldg(&th[(size_t)row * C4 + lane]));
        float4 bb = b4[lane];
        acc.x = bb.x + s2 * t.x; acc.y = bb.y + s2 * t.y;
        acc.z = bb.z + s2 * t.z; acc.w = bb.w + s2 * t.w;
    }

    int j = beg;
    for (; j + 3 < end; j += 4) {
        int2 p0 = __ldg(&g_epair[j]);
        int2 p1 = __ldg(&g_epair[j + 1]);
        int2 p2 = __ldg(&g_epair[j + 2]);
        int2 p3 = __ldg(&g_epair[j + 3]);
        if (act) {
            float4 v0 = h4_to_f4(__ldg(&th[(size_t)p0.x * C4 + lane]));
            float4 v1 = h4_to_f4(__ldg(&th[(size_t)p1.x * C4 + lane]));
            float4 v2 = h4_to_f4(__ldg(&th[(size_t)p2.x * C4 + lane]));
            float4 v3 = h4_to_f4(__ldg(&th[(size_t)p3.x * C4 + lane]));
            float n0 = __int_as_float(p0.y), n1 = __int_as_float(p1.y);
            float n2 = __int_as_float(p2.y), n3 = __int_as_float(p3.y);
            acc.x += n0 * v0.x + n1 * v1.x + n2 * v2.x + n3 * v3.x;
            acc.y += n0 * v0.y + n1 * v1.y + n2 * v2.y + n3 * v3.y;
            acc.z += n0 * v0.z + n1 * v1.z + n2 * v2.z + n3 * v3.z;
            acc.w += n0 * v0.w + n1 * v1.w + n2 * v2.w + n3 * v3.w;
        }
    }
    for (; j < end; j++) {
        int2 p0 = __ldg(&g_epair[j]);
        if (act) {
            float4 v0 = h4_to_f4(__ldg(&th[(size_t)p0.x * C4 + lane]));
            float n0 = __int_as_float(p0.y);
            acc.x += n0 * v0.x; acc.y += n0 * v0.y;
            acc.z += n0 * v0.z; acc.w += n0 * v0.w;
        }
    }

    // row-wise log_softmax across the 16-lane group
    float m = act ? fmaxf(fmaxf(acc.x, acc.y), fmaxf(acc.z, acc.w)) : -INFINITY;
#pragma unroll
    for (int k = 8; k >= 1; k >>= 1)
        m = fmaxf(m, __shfl_xor_sync(0xffffffffu, m, k, 16));
    float s = act ? (__expf(acc.x - m) + __expf(acc.y - m) +
                     __expf(acc.z - m) + __expf(acc.w - m)) : 0.f;
#pragma unroll
    for (int k = 8; k >= 1; k >>= 1)
        s += __shfl_xor_sync(0xffffffffu, s, k, 16);
    float l = m + logf(s);
    if (act) {
        reinterpret_cast<float4*>(outp)[(size_t)row * C4 + lane] =
            make_float4(acc.x - l, acc.y - l, acc.z - l, acc.w - l);
    }
}

// ---------------------------------------------------------------------------
// launcher: CSR build || gemm1, then fused agg+gemm x2, then agg+lsm
// ---------------------------------------------------------------------------
extern "C" void kernel_launch(void* const* d_in, const int* in_sizes, int n_in,
                              void* d_out, int out_size) {
    const float* x  = (const float*)d_in[0];
    const int*   ei = (const int*)d_in[1];
    const float* W1 = (const float*)d_in[2];
    const float* b1 = (const float*)d_in[3];
    const float* Wh = (const float*)d_in[4];
    const float* bh = (const float*)d_in[5];
    const float* W2 = (const float*)d_in[6];
    const float* b2 = (const float*)d_in[7];
    float* out = (float*)d_out;

    int N = in_sizes[0] / IN_C;
    int E = in_sizes[1] / 2;
    const int* src = ei;
    const int* dst = ei + E;

    uint2 *p_A, *p_B;
    int* p_deg;
    cudaGetSymbolAddress((void**)&p_A, g_bufA);
    cudaGetSymbolAddress((void**)&p_B, g_bufB);
    cudaGetSymbolAddress((void**)&p_deg, g_deg);

    static cudaStream_t s2 = nullptr;
    static cudaEvent_t evFork = nullptr, evJoin = nullptr;
    if (!s2) {
        cudaStreamCreateWithFlags(&s2, cudaStreamNonBlocking);
        cudaEventCreateWithFlags(&evFork, cudaEventDisableTiming);
        cudaEventCreateWithFlags(&evJoin, cudaEventDisableTiming);
    }

    const int T = 256;
    int nb_N = (N + T - 1) / T;
    int nb_E = (E + T - 1) / T;
    int nb_G = (N + 127) / 128;   // gemm1: 128 rows/block
    int nb_A = (N + 15) / 16;     // fused/aggregate: 16 rows/block

    // ---- fork: layer-1 GEMM (x -> A, fp16) on s2, overlapping CSR build ----
    cudaEventRecord(evFork, 0);
    cudaStreamWaitEvent(s2, evFork, 0);
    gemmh_kernel<IN_C, HID_C, false><<<nb_G, T, 0, s2>>>(x, W1, p_A, N);
    cudaEventRecord(evJoin, s2);

    // ---- CSR build on default stream ----
    cudaMemsetAsync(p_deg, 0, (size_t)N * sizeof(int), 0);
    deg_kernel<<<nb_E, T>>>(dst, E);
    scan_block_kernel<<<SCAN_NB, SCAN_BS>>>(N);   // also computes dinv
    add_off_kernel<<<nb_N, T>>>(N, E);            // folds block-sum prefix in
    fill_kernel<<<nb_E, T>>>(src, dst, E);

    // ---- K2: agg(A)+b1, relu, @Wh -> B ----
    cudaStreamWaitEvent(0, evJoin, 0);
    fused_agg_gemm_kernel<HID_C><<<nb_A, T>>>(p_A, b1, Wh, p_B, N);

    // ---- K3: agg(B)+bh, relu, @W2 -> A (40-wide rows) ----
    fused_agg_gemm_kernel<OUT_C><<<nb_A, T>>>(p_B, bh, W2, p_A, N);

    // ---- K4: agg(A,40)+b2 + log_softmax -> out ----
    aggregateh_lsm_kernel<OUT_C / 4><<<nb_A, T>>>(p_A, b2, out, N);
}

// round 13
// speedup vs baseline: 1.1663x; 1.1663x over previous
#include <cuda_runtime.h>
#include <cuda_fp16.h>
#include <math.h>

#define N_NODES 100000
#define N_EDGES 1600000
#define IN_C 64
#define HID_C 64
#define OUT_C 40
#define SCAN_BS 512
#define SCAN_NB ((N_NODES + SCAN_BS - 1) / SCAN_BS)   // 196

// Scratch (allocation-free rule: __device__ globals)
__device__ uint2 g_tmph[(size_t)N_NODES * (HID_C / 4)]; // fp16 messages (all layers)
__device__ float g_h[(size_t)N_NODES * HID_C];          // aggregated layer output / next input
__device__ float g_dinv[N_NODES];
__device__ int   g_deg[N_NODES];
__device__ int   g_rowptr[N_NODES + 1];
__device__ int   g_cursor[N_NODES];
__device__ int   g_bsum[SCAN_NB];
__device__ int2  g_epair[N_EDGES];                 // {src, norm(bits)} binned by dst

// ---------------------------------------------------------------------------
// packed f32x2 helpers (Blackwell: 1 instr = 2 fp32 MACs)
// ---------------------------------------------------------------------------
__device__ __forceinline__ void fma2(unsigned long long& d, unsigned long long a,
                                     unsigned long long b) {
    asm("fma.rn.f32x2 %0, %1, %2, %0;" : "+l"(d) : "l"(a), "l"(b));
}
__device__ __forceinline__ unsigned long long bcast2(float x) {
    unsigned long long p;
    asm("mov.b64 %0, {%1, %1};" : "=l"(p) : "f"(x));
    return p;
}
__device__ __forceinline__ unsigned long long pair2(float lo, float hi) {
    unsigned long long p;
    asm("mov.b64 %0, {%1, %2};" : "=l"(p) : "f"(lo), "f"(hi));
    return p;
}
__device__ __forceinline__ void unpack2(unsigned long long p, float& lo, float& hi) {
    asm("mov.b64 {%0, %1}, %2;" : "=f"(lo), "=f"(hi) : "l"(p));
}

// ---------------------------------------------------------------------------
// degree
// ---------------------------------------------------------------------------
__global__ void deg_kernel(const int* __restrict__ dst, int E) {
    int i = blockIdx.x * blockDim.x + threadIdx.x;
    if (i < E) atomicAdd(&g_deg[dst[i]], 1);
}

// ---------------------------------------------------------------------------
// CSR build: block-wise exclusive scan of deg -> rowptr (dinv fused here)
// ---------------------------------------------------------------------------
__global__ void scan_block_kernel(int N) {
    __shared__ int s[SCAN_BS];
    int i = blockIdx.x * SCAN_BS + threadIdx.x;
    int v = (i < N) ? g_deg[i] : 0;
    if (i < N) g_dinv[i] = rsqrtf((float)(v + 1));     // +1 self loop; always > 0
    s[threadIdx.x] = v;
    __syncthreads();
#pragma unroll
    for (int off = 1; off < SCAN_BS; off <<= 1) {
        int t = 0;
        if (threadIdx.x >= off) t = s[threadIdx.x - off];
        __syncthreads();
        if (threadIdx.x >= off) s[threadIdx.x] += t;
        __syncthreads();
    }
    if (i < N) g_rowptr[i] = s[threadIdx.x] - v;       // exclusive, block-local
    if (threadIdx.x == SCAN_BS - 1) g_bsum[blockIdx.x] = s[SCAN_BS - 1];
}

// add block offsets (each block redundantly scans the 196 block sums in smem)
__global__ void add_off_kernel(int N, int E) {
    __shared__ int s[256];
    int t = threadIdx.x;
    int v = (t < SCAN_NB) ? g_bsum[t] : 0;
    s[t] = v;
    __syncthreads();
#pragma unroll
    for (int off = 1; off < 256; off <<= 1) {
        int u = 0;
        if (t >= off) u = s[t - off];
        __syncthreads();
        if (t >= off) s[t] += u;
        __syncthreads();
    }
    int i = blockIdx.x * blockDim.x + threadIdx.x;
    if (i < N) {
        int b = i >> 9;
        int off = (b > 0) ? s[b - 1] : 0;          // exclusive prefix of bsum
        int r = g_rowptr[i] + off;
        g_rowptr[i] = r;
        g_cursor[i] = r;
    }
    if (i == 0) g_rowptr[N] = E;
}

__global__ void fill_kernel(const int* __restrict__ src, const int* __restrict__ dst, int E) {
    int e = blockIdx.x * blockDim.x + threadIdx.x;
    if (e >= E) return;
    int s = src[e], d = dst[e];
    float nrm = g_dinv[s] * g_dinv[d];
    int pos = atomicAdd(&g_cursor[d], 1);
    g_epair[pos] = make_int2(s, __float_as_int(nrm));
}

// ---------------------------------------------------------------------------
// dense transform, fp16 output: fp32 f32x2 accumulate, one rounding on store.
// 2 threads/row, interleaved chunks. Row = OUT/4 uint2 (4 halves each).
// ---------------------------------------------------------------------------
template <int IN, int OUT, bool RELU>
__global__ void __launch_bounds__(256) gemmh_kernel(const float* __restrict__ X,
                                                    const float* __restrict__ W,
                                                    uint2* __restrict__ Yh, int N) {
    constexpr int NJ = OUT / 8;   // float4 chunks per thread (8 for 64, 5 for 40)
    __shared__ __align__(16) float Ws[IN * OUT];
    for (int i = threadIdx.x; i < IN * OUT; i += blockDim.x) Ws[i] = W[i];
    __syncthreads();

    int half = threadIdx.x & 1;
    int r = blockIdx.x * 128 + (threadIdx.x >> 1);
    if (r >= N) return;

    unsigned long long acc[2 * NJ];
#pragma unroll
    for (int j = 0; j < 2 * NJ; j++) acc[j] = 0ull;

    const float4* xr = reinterpret_cast<const float4*>(X + (size_t)r * IN);
#pragma unroll 4
    for (int k4 = 0; k4 < IN / 4; k4++) {
        float4 xv = xr[k4];
        if (RELU) {
            xv.x = fmaxf(xv.x, 0.f); xv.y = fmaxf(xv.y, 0.f);
            xv.z = fmaxf(xv.z, 0.f); xv.w = fmaxf(xv.w, 0.f);
        }
        float xs[4] = {xv.x, xv.y, xv.z, xv.w};
#pragma unroll
        for (int kk = 0; kk < 4; kk++) {
            unsigned long long xx = bcast2(xs[kk]);
            const float4* wr = reinterpret_cast<const float4*>(Ws + (4 * k4 + kk) * OUT);
#pragma unroll
            for (int j = 0; j < NJ; j++) {
                float4 w = wr[2 * j + half];
                fma2(acc[2 * j],     xx, pair2(w.x, w.y));
                fma2(acc[2 * j + 1], xx, pair2(w.z, w.w));
            }
        }
    }
    uint2* yr = Yh + (size_t)r * (OUT / 4);
#pragma unroll
    for (int j = 0; j < NJ; j++) {
        float l0, h0, l1, h1;
        unpack2(acc[2 * j],     l0, h0);
        unpack2(acc[2 * j + 1], l1, h1);
        __half2 a = __floats2half2_rn(l0, h0);
        __half2 b = __floats2half2_rn(l1, h1);
        uint2 o;
        o.x = *reinterpret_cast<unsigned int*>(&a);
        o.y = *reinterpret_cast<unsigned int*>(&b);
        yr[2 * j + half] = o;
    }
}

__device__ __forceinline__ float4 h4_to_f4(uint2 raw) {
    __half2 a = *reinterpret_cast<__half2*>(&raw.x);
    __half2 b = *reinterpret_cast<__half2*>(&raw.y);
    float2 fa = __half22float2(a);
    float2 fb = __half22float2(b);
    return make_float4(fa.x, fa.y, fb.x, fb.y);
}

// ---------------------------------------------------------------------------
// CSR aggregate over fp16 messages (round-9 proven loop structure):
// 16 lanes per row, lane handles 4 channels (one uint2); fp32 accumulate;
// 4-way edge unroll. Fused self-loop/bias init; optional fused log_softmax.
// ---------------------------------------------------------------------------
template <int C4, bool LSM>
__global__ void aggregateh_kernel(const uint2* __restrict__ th, const float* __restrict__ b,
                                  float* __restrict__ outp, int N) {
    int g    = blockIdx.x * 16 + (threadIdx.x >> 4);
    int lane = threadIdx.x & 15;
    bool rowok = (g < N);
    int row  = rowok ? g : 0;
    bool act = rowok && (lane < C4);

    const float4* b4 = reinterpret_cast<const float4*>(b);

    float4 acc = make_float4(0.f, 0.f, 0.f, 0.f);
    int beg = 0, end = 0;
    if (rowok) {
        beg = g_rowptr[row];
        end = g_rowptr[row + 1];
    }
    if (act) {
        float di = g_dinv[row];
        float s2 = di * di;
        float4 t = h4_to_f4(__ldg(&th[(size_t)row * C4 + lane]));
        float4 bb = b4[lane];
        acc.x = bb.x + s2 * t.x; acc.y = bb.y + s2 * t.y;
        acc.z = bb.z + s2 * t.z; acc.w = bb.w + s2 * t.w;
    }

    int j = beg;
    for (; j + 3 < end; j += 4) {                       // 4-way unroll for MLP
        int2 p0 = __ldg(&g_epair[j]);
        int2 p1 = __ldg(&g_epair[j + 1]);
        int2 p2 = __ldg(&g_epair[j + 2]);
        int2 p3 = __ldg(&g_epair[j + 3]);
        if (act) {
            float4 v0 = h4_to_f4(__ldg(&th[(size_t)p0.x * C4 + lane]));
            float4 v1 = h4_to_f4(__ldg(&th[(size_t)p1.x * C4 + lane]));
            float4 v2 = h4_to_f4(__ldg(&th[(size_t)p2.x * C4 + lane]));
            float4 v3 = h4_to_f4(__ldg(&th[(size_t)p3.x * C4 + lane]));
            float n0 = __int_as_float(p0.y), n1 = __int_as_float(p1.y);
            float n2 = __int_as_float(p2.y), n3 = __int_as_float(p3.y);
            acc.x += n0 * v0.x + n1 * v1.x + n2 * v2.x + n3 * v3.x;
            acc.y += n0 * v0.y + n1 * v1.y + n2 * v2.y + n3 * v3.y;
            acc.z += n0 * v0.z + n1 * v1.z + n2 * v2.z + n3 * v3.z;
            acc.w += n0 * v0.w + n1 * v1.w + n2 * v2.w + n3 * v3.w;
        }
    }
    for (; j < end; j++) {
        int2 p0 = __ldg(&g_epair[j]);
        if (act) {
            float4 v0 = h4_to_f4(__ldg(&th[(size_t)p0.x * C4 + lane]));
            float n0 = __int_as_float(p0.y);
            acc.x += n0 * v0.x; acc.y += n0 * v0.y;
            acc.z += n0 * v0.z; acc.w += n0 * v0.w;
        }
    }

    if (LSM) {
        // row-wise log_softmax across the 16-lane group (width-16 butterfly)
        float m = act ? fmaxf(fmaxf(acc.x, acc.y), fmaxf(acc.z, acc.w)) : -INFINITY;
#pragma unroll
        for (int k = 8; k >= 1; k >>= 1)
            m = fmaxf(m, __shfl_xor_sync(0xffffffffu, m, k, 16));
        float s = act ? (__expf(acc.x - m) + __expf(acc.y - m) +
                         __expf(acc.z - m) + __expf(acc.w - m)) : 0.f;
#pragma unroll
        for (int k = 8; k >= 1; k >>= 1)
            s += __shfl_xor_sync(0xffffffffu, s, k, 16);
        float l = m + logf(s);
        if (act) {
            reinterpret_cast<float4*>(outp)[(size_t)row * C4 + lane] =
                make_float4(acc.x - l, acc.y - l, acc.z - l, acc.w - l);
        }
    } else if (act) {
        reinterpret_cast<float4*>(outp)[(size_t)row * C4 + lane] = acc;
    }
}

// ---------------------------------------------------------------------------
// launcher: CSR build on default stream, layer-1 GEMM forked onto s2
// ---------------------------------------------------------------------------
extern "C" void kernel_launch(void* const* d_in, const int* in_sizes, int n_in,
                              void* d_out, int out_size) {
    const float* x  = (const float*)d_in[0];
    const int*   ei = (const int*)d_in[1];
    const float* W1 = (const float*)d_in[2];
    const float* b1 = (const float*)d_in[3];
    const float* Wh = (const float*)d_in[4];
    const float* bh = (const float*)d_in[5];
    const float* W2 = (const float*)d_in[6];
    const float* b2 = (const float*)d_in[7];
    float* out = (float*)d_out;

    int N = in_sizes[0] / IN_C;
    int E = in_sizes[1] / 2;
    const int* src = ei;
    const int* dst = ei + E;

    float* p_h;
    uint2* p_tmph;
    int* p_deg;
    cudaGetSymbolAddress((void**)&p_h, g_h);
    cudaGetSymbolAddress((void**)&p_tmph, g_tmph);
    cudaGetSymbolAddress((void**)&p_deg, g_deg);

    static cudaStream_t s2 = nullptr;
    static cudaEvent_t evFork = nullptr, evJoin = nullptr;
    if (!s2) {
        cudaStreamCreateWithFlags(&s2, cudaStreamNonBlocking);
        cudaEventCreateWithFlags(&evFork, cudaEventDisableTiming);
        cudaEventCreateWithFlags(&evJoin, cudaEventDisableTiming);
    }

    const int T = 256;
    int nb_N = (N + T - 1) / T;
    int nb_E = (E + T - 1) / T;
    int nb_G = (N + 127) / 128;   // gemm: 128 rows/block
    int nb_A = (N + 15) / 16;     // aggregate: 16 rows/block

    // ---- fork: layer-1 GEMM (fp16 out) on s2, overlapping CSR build ----
    cudaEventRecord(evFork, 0);
    cudaStreamWaitEvent(s2, evFork, 0);
    gemmh_kernel<IN_C, HID_C, false><<<nb_G, T, 0, s2>>>(x, W1, p_tmph, N);
    cudaEventRecord(evJoin, s2);

    // ---- CSR build on default stream ----
    cudaMemsetAsync(p_deg, 0, (size_t)N * sizeof(int), 0);
    deg_kernel<<<nb_E, T>>>(dst, E);
    scan_block_kernel<<<SCAN_NB, SCAN_BS>>>(N);   // also computes dinv
    add_off_kernel<<<nb_N, T>>>(N, E);            // folds block-sum prefix in
    fill_kernel<<<nb_E, T>>>(src, dst, E);

    // ---- layer 1: aggregate fp16 messages -> fp32 h ----
    cudaStreamWaitEvent(0, evJoin, 0);
    aggregateh_kernel<HID_C / 4, false><<<nb_A, T>>>(p_tmph, b1, p_h, N);

    // ---- layer 2 ----
    gemmh_kernel<HID_C, HID_C, true><<<nb_G, T>>>(p_h, Wh, p_tmph, N);
    aggregateh_kernel<HID_C / 4, false><<<nb_A, T>>>(p_tmph, bh, p_h, N);

    // ---- layer 3 (40-wide, fp16 messages) + fused log_softmax ----
    gemmh_kernel<HID_C, OUT_C, true><<<nb_G, T>>>(p_h, W2, p_tmph, N);
    aggregateh_kernel<OUT_C / 4, true><<<nb_A, T>>>(p_tmph, b2, out, N);
}

// round 14
// speedup vs baseline: 1.1971x; 1.0265x over previous
#include <cuda_runtime.h>
#include <cuda_fp16.h>
#include <math.h>

#define N_NODES 100000
#define N_EDGES 1600000
#define IN_C 64
#define HID_C 64
#define OUT_C 40
#define SCAN_BS 512
#define SCAN_NB ((N_NODES + SCAN_BS - 1) / SCAN_BS)   // 196

// Scratch (allocation-free rule: __device__ globals)
__device__ uint2 g_msg[(size_t)N_NODES * (HID_C / 4)]; // fp16 pre-scaled messages (dinv[src]*y)
__device__ uint2 g_hh[(size_t)N_NODES * (HID_C / 4)];  // fp16 aggregated h (gemm input)
__device__ float g_dinv[N_NODES];
__device__ int   g_deg[N_NODES];
__device__ int   g_rowptr[N_NODES + 1];
__device__ int   g_cursor[N_NODES];
__device__ int   g_bsum[SCAN_NB];
__device__ int   g_esrc[N_EDGES];                  // src index only, binned by dst

// ---------------------------------------------------------------------------
// packed f32x2 helpers (Blackwell: 1 instr = 2 fp32 MACs)
// ---------------------------------------------------------------------------
__device__ __forceinline__ void fma2(unsigned long long& d, unsigned long long a,
                                     unsigned long long b) {
    asm("fma.rn.f32x2 %0, %1, %2, %0;" : "+l"(d) : "l"(a), "l"(b));
}
__device__ __forceinline__ unsigned long long bcast2(float x) {
    unsigned long long p;
    asm("mov.b64 %0, {%1, %1};" : "=l"(p) : "f"(x));
    return p;
}
__device__ __forceinline__ unsigned long long pair2(float lo, float hi) {
    unsigned long long p;
    asm("mov.b64 %0, {%1, %2};" : "=l"(p) : "f"(lo), "f"(hi));
    return p;
}
__device__ __forceinline__ void unpack2(unsigned long long p, float& lo, float& hi) {
    asm("mov.b64 {%0, %1}, %2;" : "=f"(lo), "=f"(hi) : "l"(p));
}

__device__ __forceinline__ float4 h4_to_f4(uint2 raw) {
    __half2 a = *reinterpret_cast<__half2*>(&raw.x);
    __half2 b = *reinterpret_cast<__half2*>(&raw.y);
    float2 fa = __half22float2(a);
    float2 fb = __half22float2(b);
    return make_float4(fa.x, fa.y, fb.x, fb.y);
}
__device__ __forceinline__ uint2 f4_to_h4(float4 v) {
    __half2 a = __floats2half2_rn(v.x, v.y);
    __half2 b = __floats2half2_rn(v.z, v.w);
    uint2 o;
    o.x = *reinterpret_cast<unsigned int*>(&a);
    o.y = *reinterpret_cast<unsigned int*>(&b);
    return o;
}

// ---------------------------------------------------------------------------
// degree
// ---------------------------------------------------------------------------
__global__ void deg_kernel(const int* __restrict__ dst, int E) {
    int i = blockIdx.x * blockDim.x + threadIdx.x;
    if (i < E) atomicAdd(&g_deg[dst[i]], 1);
}

// ---------------------------------------------------------------------------
// CSR build: block-wise exclusive scan of deg -> rowptr (dinv fused here)
// ---------------------------------------------------------------------------
__global__ void scan_block_kernel(int N) {
    __shared__ int s[SCAN_BS];
    int i = blockIdx.x * SCAN_BS + threadIdx.x;
    int v = (i < N) ? g_deg[i] : 0;
    if (i < N) g_dinv[i] = rsqrtf((float)(v + 1));     // +1 self loop; always > 0
    s[threadIdx.x] = v;
    __syncthreads();
#pragma unroll
    for (int off = 1; off < SCAN_BS; off <<= 1) {
        int t = 0;
        if (threadIdx.x >= off) t = s[threadIdx.x - off];
        __syncthreads();
        if (threadIdx.x >= off) s[threadIdx.x] += t;
        __syncthreads();
    }
    if (i < N) g_rowptr[i] = s[threadIdx.x] - v;       // exclusive, block-local
    if (threadIdx.x == SCAN_BS - 1) g_bsum[blockIdx.x] = s[SCAN_BS - 1];
}

// add block offsets (each block redundantly scans the 196 block sums in smem)
__global__ void add_off_kernel(int N, int E) {
    __shared__ int s[256];
    int t = threadIdx.x;
    int v = (t < SCAN_NB) ? g_bsum[t] : 0;
    s[t] = v;
    __syncthreads();
#pragma unroll
    for (int off = 1; off < 256; off <<= 1) {
        int u = 0;
        if (t >= off) u = s[t - off];
        __syncthreads();
        if (t >= off) s[t] += u;
        __syncthreads();
    }
    int i = blockIdx.x * blockDim.x + threadIdx.x;
    if (i < N) {
        int b = i >> 9;
        int off = (b > 0) ? s[b - 1] : 0;          // exclusive prefix of bsum
        int r = g_rowptr[i] + off;
        g_rowptr[i] = r;
        g_cursor[i] = r;
    }
    if (i == 0) g_rowptr[N] = E;
}

// bin edges by dst; store src index only (norm is factored out)
__global__ void fill_kernel(const int* __restrict__ src, const int* __restrict__ dst, int E) {
    int e = blockIdx.x * blockDim.x + threadIdx.x;
    if (e >= E) return;
    int d = dst[e];
    int pos = atomicAdd(&g_cursor[d], 1);
    g_esrc[pos] = src[e];
}

// ---------------------------------------------------------------------------
// dense transform, fp16 pre-scaled message output:
//   msg'[r,:] = dinv[r] * ((relu?)X[r,:] @ W)
// fp32 f32x2 accumulate; 2 threads/row, interleaved chunks.
// INHALF: X is fp16 (uint2 rows) else fp32 (float4 rows).
// ---------------------------------------------------------------------------
template <int IN, int OUT, bool RELU, bool INHALF>
__global__ void __launch_bounds__(256) gemmh_kernel(const void* __restrict__ Xv,
                                                    const float* __restrict__ W,
                                                    uint2* __restrict__ Yh, int N) {
    constexpr int NJ = OUT / 8;   // float4 chunks per thread (8 for 64, 5 for 40)
    __shared__ __align__(16) float Ws[IN * OUT];
    for (int i = threadIdx.x; i < IN * OUT; i += blockDim.x) Ws[i] = W[i];
    __syncthreads();

    int half = threadIdx.x & 1;
    int r = blockIdx.x * 128 + (threadIdx.x >> 1);
    if (r >= N) return;

    unsigned long long acc[2 * NJ];
#pragma unroll
    for (int j = 0; j < 2 * NJ; j++) acc[j] = 0ull;

    const float4* xr4 = reinterpret_cast<const float4*>(Xv) + (size_t)r * (IN / 4);
    const uint2*  xrh = reinterpret_cast<const uint2*>(Xv)  + (size_t)r * (IN / 4);
#pragma unroll 4
    for (int k4 = 0; k4 < IN / 4; k4++) {
        float4 xv = INHALF ? h4_to_f4(xrh[k4]) : xr4[k4];
        if (RELU) {
            xv.x = fmaxf(xv.x, 0.f); xv.y = fmaxf(xv.y, 0.f);
            xv.z = fmaxf(xv.z, 0.f); xv.w = fmaxf(xv.w, 0.f);
        }
        float xs[4] = {xv.x, xv.y, xv.z, xv.w};
#pragma unroll
        for (int kk = 0; kk < 4; kk++) {
            unsigned long long xx = bcast2(xs[kk]);
            const float4* wr = reinterpret_cast<const float4*>(Ws + (4 * k4 + kk) * OUT);
#pragma unroll
            for (int j = 0; j < NJ; j++) {
                float4 w = wr[2 * j + half];
                fma2(acc[2 * j],     xx, pair2(w.x, w.y));
                fma2(acc[2 * j + 1], xx, pair2(w.z, w.w));
            }
        }
    }
    float di = g_dinv[r];                    // pre-scale message by dinv[src]
    uint2* yr = Yh + (size_t)r * (OUT / 4);
#pragma unroll
    for (int j = 0; j < NJ; j++) {
        float l0, h0, l1, h1;
        unpack2(acc[2 * j],     l0, h0);
        unpack2(acc[2 * j + 1], l1, h1);
        yr[2 * j + half] = f4_to_h4(make_float4(di * l0, di * h0, di * l1, di * h1));
    }
}

// ---------------------------------------------------------------------------
// CSR aggregate over pre-scaled fp16 messages (round-9 proven loop structure):
//   sum = msg'[row] + Sum_e msg'[src_e];  res = b + dinv[row] * sum
// 16 lanes per row, lane handles 4 channels; fp32 accumulate; 4-way unroll.
// MODE 0: write fp16 h (gemm input). MODE 1: fused log_softmax, fp32 out.
// ---------------------------------------------------------------------------
template <int C4, int MODE>
__global__ void aggregateh_kernel(const uint2* __restrict__ th, const float* __restrict__ b,
                                  void* __restrict__ outp, int N) {
    int g    = blockIdx.x * 16 + (threadIdx.x >> 4);
    int lane = threadIdx.x & 15;
    bool rowok = (g < N);
    int row  = rowok ? g : 0;
    bool act = rowok && (lane < C4);

    const float4* b4 = reinterpret_cast<const float4*>(b);

    float4 acc = make_float4(0.f, 0.f, 0.f, 0.f);
    int beg = 0, end = 0;
    if (rowok) {
        beg = g_rowptr[row];
        end = g_rowptr[row + 1];
    }
    if (act)   // self-loop message
        acc = h4_to_f4(__ldg(&th[(size_t)row * C4 + lane]));

    int j = beg;
    for (; j + 3 < end; j += 4) {                       // 4-way unroll for MLP
        int s0 = __ldg(&g_esrc[j]);
        int s1 = __ldg(&g_esrc[j + 1]);
        int s2 = __ldg(&g_esrc[j + 2]);
        int s3 = __ldg(&g_esrc[j + 3]);
        if (act) {
            float4 v0 = h4_to_f4(__ldg(&th[(size_t)s0 * C4 + lane]));
            float4 v1 = h4_to_f4(__ldg(&th[(size_t)s1 * C4 + lane]));
            float4 v2 = h4_to_f4(__ldg(&th[(size_t)s2 * C4 + lane]));
            float4 v3 = h4_to_f4(__ldg(&th[(size_t)s3 * C4 + lane]));
            acc.x += (v0.x + v1.x) + (v2.x + v3.x);
            acc.y += (v0.y + v1.y) + (v2.y + v3.y);
            acc.z += (v0.z + v1.z) + (v2.z + v3.z);
            acc.w += (v0.w + v1.w) + (v2.w + v3.w);
        }
    }
    for (; j < end; j++) {
        int s0 = __ldg(&g_esrc[j]);
        if (act) {
            float4 v0 = h4_to_f4(__ldg(&th[(size_t)s0 * C4 + lane]));
            acc.x += v0.x; acc.y += v0.y;
            acc.z += v0.z; acc.w += v0.w;
        }
    }

    float4 res = make_float4(0.f, 0.f, 0.f, 0.f);
    if (act) {
        float di = g_dinv[row];
        float4 bb = b4[lane];
        res.x = bb.x + di * acc.x; res.y = bb.y + di * acc.y;
        res.z = bb.z + di * acc.z; res.w = bb.w + di * acc.w;
    }

    if (MODE == 0) {
        if (act)
            reinterpret_cast<uint2*>(outp)[(size_t)row * C4 + lane] = f4_to_h4(res);
    } else {
        // row-wise log_softmax across the 16-lane group (width-16 butterfly)
        float m = act ? fmaxf(fmaxf(res.x, res.y), fmaxf(res.z, res.w)) : -INFINITY;
#pragma unroll
        for (int k = 8; k >= 1; k >>= 1)
            m = fmaxf(m, __shfl_xor_sync(0xffffffffu, m, k, 16));
        float s = act ? (__expf(res.x - m) + __expf(res.y - m) +
                         __expf(res.z - m) + __expf(res.w - m)) : 0.f;
#pragma unroll
        for (int k = 8; k >= 1; k >>= 1)
            s += __shfl_xor_sync(0xffffffffu, s, k, 16);
        float l = m + logf(s);
        if (act) {
            reinterpret_cast<float4*>(outp)[(size_t)row * C4 + lane] =
                make_float4(res.x - l, res.y - l, res.z - l, res.w - l);
        }
    }
}

// ---------------------------------------------------------------------------
// launcher: deg+scan(dinv) first; then gemm1 on s2 || add_off+fill on default
// ---------------------------------------------------------------------------
extern "C" void kernel_launch(void* const* d_in, const int* in_sizes, int n_in,
                              void* d_out, int out_size) {
    const float* x  = (const float*)d_in[0];
    const int*   ei = (const int*)d_in[1];
    const float* W1 = (const float*)d_in[2];
    const float* b1 = (const float*)d_in[3];
    const float* Wh = (const float*)d_in[4];
    const float* bh = (const float*)d_in[5];
    const float* W2 = (const float*)d_in[6];
    const float* b2 = (const float*)d_in[7];
    float* out = (float*)d_out;

    int N = in_sizes[0] / IN_C;
    int E = in_sizes[1] / 2;
    const int* src = ei;
    const int* dst = ei + E;

    uint2 *p_msg, *p_hh;
    int* p_deg;
    cudaGetSymbolAddress((void**)&p_msg, g_msg);
    cudaGetSymbolAddress((void**)&p_hh, g_hh);
    cudaGetSymbolAddress((void**)&p_deg, g_deg);

    static cudaStream_t s2 = nullptr;
    static cudaEvent_t evDinv = nullptr, evJoin = nullptr;
    if (!s2) {
        cudaStreamCreateWithFlags(&s2, cudaStreamNonBlocking);
        cudaEventCreateWithFlags(&evDinv, cudaEventDisableTiming);
        cudaEventCreateWithFlags(&evJoin, cudaEventDisableTiming);
    }

    const int T = 256;
    int nb_N = (N + T - 1) / T;
    int nb_E = (E + T - 1) / T;
    int nb_G = (N + 127) / 128;   // gemm: 128 rows/block
    int nb_A = (N + 15) / 16;     // aggregate: 16 rows/block

    // ---- dinv chain on default stream ----
    cudaMemsetAsync(p_deg, 0, (size_t)N * sizeof(int), 0);
    deg_kernel<<<nb_E, T>>>(dst, E);
    scan_block_kernel<<<SCAN_NB, SCAN_BS>>>(N);   // computes dinv + block sums
    cudaEventRecord(evDinv, 0);

    // ---- fork: layer-1 GEMM (needs dinv for output pre-scale) on s2 ----
    cudaStreamWaitEvent(s2, evDinv, 0);
    gemmh_kernel<IN_C, HID_C, false, false><<<nb_G, T, 0, s2>>>(x, W1, p_msg, N);
    cudaEventRecord(evJoin, s2);

    // ---- rest of CSR build on default stream (overlaps gemm1) ----
    add_off_kernel<<<nb_N, T>>>(N, E);            // folds block-sum prefix in
    fill_kernel<<<nb_E, T>>>(src, dst, E);

    // ---- layer 1: aggregate -> fp16 h ----
    cudaStreamWaitEvent(0, evJoin, 0);
    aggregateh_kernel<HID_C / 4, 0><<<nb_A, T>>>(p_msg, b1, p_hh, N);

    // ---- layer 2 ----
    gemmh_kernel<HID_C, HID_C, true, true><<<nb_G, T>>>(p_hh, Wh, p_msg, N);
    aggregateh_kernel<HID_C / 4, 0><<<nb_A, T>>>(p_msg, bh, p_hh, N);

    // ---- layer 3 (40-wide) + fused log_softmax ----
    gemmh_kernel<HID_C, OUT_C, true, true><<<nb_G, T>>>(p_hh, W2, p_msg, N);
    aggregateh_kernel<OUT_C / 4, 1><<<nb_A, T>>>(p_msg, b2, out, N);
}

// round 15
// speedup vs baseline: 1.3437x; 1.1224x over previous
#include <cuda_runtime.h>
#include <cuda_fp16.h>
#include <mma.h>
#include <math.h>

using namespace nvcuda;

#define N_NODES 100000
#define N_EDGES 1600000
#define IN_C 64
#define HID_C 64
#define OUT_C 40
#define SCAN_BS 512
#define SCAN_NB ((N_NODES + SCAN_BS - 1) / SCAN_BS)   // 196

// Scratch (allocation-free rule: __device__ globals)
__device__ uint2 g_msg[(size_t)N_NODES * (HID_C / 4)]; // fp16 pre-scaled messages (dinv[src]*y)
__device__ uint2 g_hh[(size_t)N_NODES * (HID_C / 4)];  // fp16 relu(h) (gemm input)
__device__ uint2 g_xh[(size_t)N_NODES * (IN_C / 4)];   // fp16 copy of x
__device__ float g_dinv[N_NODES];
__device__ int   g_deg[N_NODES];
__device__ int   g_rowptr[N_NODES + 1];
__device__ int   g_cursor[N_NODES];
__device__ int   g_bsum[SCAN_NB];
__device__ int   g_esrc[N_EDGES];                  // src index only, binned by dst

// ---------------------------------------------------------------------------
// fp16 pack helpers
// ---------------------------------------------------------------------------
__device__ __forceinline__ float4 h4_to_f4(uint2 raw) {
    __half2 a = *reinterpret_cast<__half2*>(&raw.x);
    __half2 b = *reinterpret_cast<__half2*>(&raw.y);
    float2 fa = __half22float2(a);
    float2 fb = __half22float2(b);
    return make_float4(fa.x, fa.y, fb.x, fb.y);
}
__device__ __forceinline__ uint2 f4_to_h4(float4 v) {
    __half2 a = __floats2half2_rn(v.x, v.y);
    __half2 b = __floats2half2_rn(v.z, v.w);
    uint2 o;
    o.x = *reinterpret_cast<unsigned int*>(&a);
    o.y = *reinterpret_cast<unsigned int*>(&b);
    return o;
}

// ---------------------------------------------------------------------------
// x -> fp16 (independent of everything; runs on s2 at t=0)
// ---------------------------------------------------------------------------
__global__ void x2h_kernel(const float4* __restrict__ x4, uint2* __restrict__ xh, int n4) {
    int i = blockIdx.x * blockDim.x + threadIdx.x;
    if (i < n4) xh[i] = f4_to_h4(x4[i]);
}

// ---------------------------------------------------------------------------
// degree
// ---------------------------------------------------------------------------
__global__ void deg_kernel(const int* __restrict__ dst, int E) {
    int i = blockIdx.x * blockDim.x + threadIdx.x;
    if (i < E) atomicAdd(&g_deg[dst[i]], 1);
}

// ---------------------------------------------------------------------------
// CSR build: block-wise exclusive scan of deg -> rowptr (dinv fused here)
// ---------------------------------------------------------------------------
__global__ void scan_block_kernel(int N) {
    __shared__ int s[SCAN_BS];
    int i = blockIdx.x * SCAN_BS + threadIdx.x;
    int v = (i < N) ? g_deg[i] : 0;
    if (i < N) g_dinv[i] = rsqrtf((float)(v + 1));     // +1 self loop; always > 0
    s[threadIdx.x] = v;
    __syncthreads();
#pragma unroll
    for (int off = 1; off < SCAN_BS; off <<= 1) {
        int t = 0;
        if (threadIdx.x >= off) t = s[threadIdx.x - off];
        __syncthreads();
        if (threadIdx.x >= off) s[threadIdx.x] += t;
        __syncthreads();
    }
    if (i < N) g_rowptr[i] = s[threadIdx.x] - v;       // exclusive, block-local
    if (threadIdx.x == SCAN_BS - 1) g_bsum[blockIdx.x] = s[SCAN_BS - 1];
}

// add block offsets (each block redundantly scans the 196 block sums in smem)
__global__ void add_off_kernel(int N, int E) {
    __shared__ int s[256];
    int t = threadIdx.x;
    int v = (t < SCAN_NB) ? g_bsum[t] : 0;
    s[t] = v;
    __syncthreads();
#pragma unroll
    for (int off = 1; off < 256; off <<= 1) {
        int u = 0;
        if (t >= off) u = s[t - off];
        __syncthreads();
        if (t >= off) s[t] += u;
        __syncthreads();
    }
    int i = blockIdx.x * blockDim.x + threadIdx.x;
    if (i < N) {
        int b = i >> 9;
        int off = (b > 0) ? s[b - 1] : 0;          // exclusive prefix of bsum
        int r = g_rowptr[i] + off;
        g_rowptr[i] = r;
        g_cursor[i] = r;
    }
    if (i == 0) g_rowptr[N] = E;
}

// bin edges by dst; store src index only (norm is factored out)
__global__ void fill_kernel(const int* __restrict__ src, const int* __restrict__ dst, int E) {
    int e = blockIdx.x * blockDim.x + threadIdx.x;
    if (e >= E) return;
    int d = dst[e];
    int pos = atomicAdd(&g_cursor[d], 1);
    g_esrc[pos] = src[e];
}

// ---------------------------------------------------------------------------
// wmma GEMM: msg'[r,:] = dinv[r] * (Xh[r,:] @ W),  Xh fp16 [N][64] row-major.
// Block = 256 threads = 8 warps; warp = 16 rows x OUTP cols (m16n16k16).
// W (fp32) staged to fp16 smem [64][OUTP] (cols >= OUT zero-padded).
// C staged via store_matrix_sync -> smem, then dinv-scaled + packed fp16.
// ---------------------------------------------------------------------------
template <int OUT, int OUTP>
__global__ void __launch_bounds__(256) gemmw_kernel(const __half* __restrict__ Xh,
                                                    const float* __restrict__ W,
                                                    uint2* __restrict__ Yh, int N) {
    constexpr int NT = OUTP / 16;     // n tiles per warp (4 or 3)
    constexpr int C4 = OUT / 4;       // uint2 per output row
    constexpr int HC = OUT / 2;       // float cols per half-lane
    constexpr int HU = C4 / 2;        // uint2 per half-lane
    __shared__ __half Ws[64 * OUTP];
    __shared__ float  Cs[8][16 * 80]; // per-warp staging, ld=80 floats

    int tid = threadIdx.x;
    for (int i = tid; i < 64 * OUTP; i += 256) {
        int k = i / OUTP, n = i % OUTP;
        Ws[i] = (n < OUT) ? __float2half(W[k * OUT + n]) : __half(0.f);
    }
    __syncthreads();

    int warp = tid >> 5;
    int lane = tid & 31;
    int row0 = (blockIdx.x * 8 + warp) * 16;
    if (row0 >= N) return;

    wmma::fragment<wmma::matrix_a, 16, 16, 16, __half, wmma::row_major> a;
    wmma::fragment<wmma::matrix_b, 16, 16, 16, __half, wmma::row_major> b;
    wmma::fragment<wmma::accumulator, 16, 16, 16, float> c[NT];
#pragma unroll
    for (int n = 0; n < NT; n++) wmma::fill_fragment(c[n], 0.f);

#pragma unroll
    for (int k = 0; k < 4; k++) {
        wmma::load_matrix_sync(a, Xh + (size_t)row0 * 64 + k * 16, 64);
#pragma unroll
        for (int n = 0; n < NT; n++) {
            wmma::load_matrix_sync(b, Ws + (k * 16) * OUTP + n * 16, OUTP);
            wmma::mma_sync(c[n], a, b, c[n]);
        }
    }

    float* cw = Cs[warp];
#pragma unroll
    for (int n = 0; n < NT; n++)
        wmma::store_matrix_sync(cw + n * 16, c[n], 80, wmma::mem_row_major);
    __syncwarp();

    // dinv-scale + fp16 pack: lane -> (row = lane/2, half = lane&1)
    int r = lane >> 1, halfc = lane & 1;
    int grow = row0 + r;
    float di = g_dinv[grow];
    const float* crow = cw + r * 80 + halfc * HC;
    uint2* yrow = Yh + (size_t)grow * C4 + halfc * HU;
#pragma unroll
    for (int j = 0; j < HU; j++) {
        float4 v = *reinterpret_cast<const float4*>(crow + 4 * j);
        yrow[j] = f4_to_h4(make_float4(di * v.x, di * v.y, di * v.z, di * v.w));
    }
}

// ---------------------------------------------------------------------------
// CSR aggregate over pre-scaled fp16 messages (round-9 proven loop structure):
//   sum = msg'[row] + Sum_e msg'[src_e];  res = b + dinv[row] * sum
// MODE 0: write fp16 relu(res) (gemm input). MODE 1: fused log_softmax, fp32.
// ---------------------------------------------------------------------------
template <int C4, int MODE>
__global__ void aggregateh_kernel(const uint2* __restrict__ th, const float* __restrict__ b,
                                  void* __restrict__ outp, int N) {
    int g    = blockIdx.x * 16 + (threadIdx.x >> 4);
    int lane = threadIdx.x & 15;
    bool rowok = (g < N);
    int row  = rowok ? g : 0;
    bool act = rowok && (lane < C4);

    const float4* b4 = reinterpret_cast<const float4*>(b);

    float4 acc = make_float4(0.f, 0.f, 0.f, 0.f);
    int beg = 0, end = 0;
    if (rowok) {
        beg = g_rowptr[row];
        end = g_rowptr[row + 1];
    }
    if (act)   // self-loop message
        acc = h4_to_f4(__ldg(&th[(size_t)row * C4 + lane]));

    int j = beg;
    for (; j + 3 < end; j += 4) {                       // 4-way unroll for MLP
        int s0 = __ldg(&g_esrc[j]);
        int s1 = __ldg(&g_esrc[j + 1]);
        int s2 = __ldg(&g_esrc[j + 2]);
        int s3 = __ldg(&g_esrc[j + 3]);
        if (act) {
            float4 v0 = h4_to_f4(__ldg(&th[(size_t)s0 * C4 + lane]));
            float4 v1 = h4_to_f4(__ldg(&th[(size_t)s1 * C4 + lane]));
            float4 v2 = h4_to_f4(__ldg(&th[(size_t)s2 * C4 + lane]));
            float4 v3 = h4_to_f4(__ldg(&th[(size_t)s3 * C4 + lane]));
            acc.x += (v0.x + v1.x) + (v2.x + v3.x);
            acc.y += (v0.y + v1.y) + (v2.y + v3.y);
            acc.z += (v0.z + v1.z) + (v2.z + v3.z);
            acc.w += (v0.w + v1.w) + (v2.w + v3.w);
        }
    }
    for (; j < end; j++) {
        int s0 = __ldg(&g_esrc[j]);
        if (act) {
            float4 v0 = h4_to_f4(__ldg(&th[(size_t)s0 * C4 + lane]));
            acc.x += v0.x; acc.y += v0.y;
            acc.z += v0.z; acc.w += v0.w;
        }
    }

    float4 res = make_float4(0.f, 0.f, 0.f, 0.f);
    if (act) {
        float di = g_dinv[row];
        float4 bb = b4[lane];
        res.x = bb.x + di * acc.x; res.y = bb.y + di * acc.y;
        res.z = bb.z + di * acc.z; res.w = bb.w + di * acc.w;
    }

    if (MODE == 0) {
        if (act) {
            // relu folded here (next gemm consumes pure A@W input)
            res.x = fmaxf(res.x, 0.f); res.y = fmaxf(res.y, 0.f);
            res.z = fmaxf(res.z, 0.f); res.w = fmaxf(res.w, 0.f);
            reinterpret_cast<uint2*>(outp)[(size_t)row * C4 + lane] = f4_to_h4(res);
        }
    } else {
        // row-wise log_softmax across the 16-lane group (width-16 butterfly)
        float m = act ? fmaxf(fmaxf(res.x, res.y), fmaxf(res.z, res.w)) : -INFINITY;
#pragma unroll
        for (int k = 8; k >= 1; k >>= 1)
            m = fmaxf(m, __shfl_xor_sync(0xffffffffu, m, k, 16));
        float s = act ? (__expf(res.x - m) + __expf(res.y - m) +
                         __expf(res.z - m) + __expf(res.w - m)) : 0.f;
#pragma unroll
        for (int k = 8; k >= 1; k >>= 1)
            s += __shfl_xor_sync(0xffffffffu, s, k, 16);
        float l = m + logf(s);
        if (act) {
            reinterpret_cast<float4*>(outp)[(size_t)row * C4 + lane] =
                make_float4(res.x - l, res.y - l, res.z - l, res.w - l);
        }
    }
}

// ---------------------------------------------------------------------------
// launcher
// ---------------------------------------------------------------------------
extern "C" void kernel_launch(void* const* d_in, const int* in_sizes, int n_in,
                              void* d_out, int out_size) {
    const float* x  = (const float*)d_in[0];
    const int*   ei = (const int*)d_in[1];
    const float* W1 = (const float*)d_in[2];
    const float* b1 = (const float*)d_in[3];
    const float* Wh = (const float*)d_in[4];
    const float* bh = (const float*)d_in[5];
    const float* W2 = (const float*)d_in[6];
    const float* b2 = (const float*)d_in[7];
    float* out = (float*)d_out;

    int N = in_sizes[0] / IN_C;
    int E = in_sizes[1] / 2;
    const int* src = ei;
    const int* dst = ei + E;

    uint2 *p_msg, *p_hh, *p_xh;
    int* p_deg;
    cudaGetSymbolAddress((void**)&p_msg, g_msg);
    cudaGetSymbolAddress((void**)&p_hh, g_hh);
    cudaGetSymbolAddress((void**)&p_xh, g_xh);
    cudaGetSymbolAddress((void**)&p_deg, g_deg);

    static cudaStream_t s2 = nullptr;
    static cudaEvent_t evDinv = nullptr, evJoin = nullptr;
    if (!s2) {
        cudaStreamCreateWithFlags(&s2, cudaStreamNonBlocking);
        cudaEventCreateWithFlags(&evDinv, cudaEventDisableTiming);
        cudaEventCreateWithFlags(&evJoin, cudaEventDisableTiming);
    }

    const int T = 256;
    int nb_N = (N + T - 1) / T;
    int nb_E = (E + T - 1) / T;
    int nb_W = (N + 127) / 128;   // wmma gemm: 128 rows/block
    int nb_A = (N + 15) / 16;     // aggregate: 16 rows/block
    int n4   = N * (IN_C / 4);

    // ---- dinv chain on default stream ----
    cudaMemsetAsync(p_deg, 0, (size_t)N * sizeof(int), 0);
    deg_kernel<<<nb_E, T>>>(dst, E);
    scan_block_kernel<<<SCAN_NB, SCAN_BS>>>(N);   // computes dinv + block sums
    cudaEventRecord(evDinv, 0);

    // ---- s2: x->fp16 at t=0, then layer-1 wmma GEMM (needs dinv) ----
    x2h_kernel<<<(n4 + T - 1) / T, T, 0, s2>>>(
        reinterpret_cast<const float4*>(x), p_xh, n4);
    cudaStreamWaitEvent(s2, evDinv, 0);
    gemmw_kernel<HID_C, 64><<<nb_W, T, 0, s2>>>(
        reinterpret_cast<const __half*>(p_xh), W1, p_msg, N);
    cudaEventRecord(evJoin, s2);

    // ---- rest of CSR build on default stream (overlaps gemm1) ----
    add_off_kernel<<<nb_N, T>>>(N, E);            // folds block-sum prefix in
    fill_kernel<<<nb_E, T>>>(src, dst, E);

    // ---- layer 1: aggregate -> fp16 relu(h) ----
    cudaStreamWaitEvent(0, evJoin, 0);
    aggregateh_kernel<HID_C / 4, 0><<<nb_A, T>>>(p_msg, b1, p_hh, N);

    // ---- layer 2 ----
    gemmw_kernel<HID_C, 64><<<nb_W, T>>>(
        reinterpret_cast<const __half*>(p_hh), Wh, p_msg, N);
    aggregateh_kernel<HID_C / 4, 0><<<nb_A, T>>>(p_msg, bh, p_hh, N);

    // ---- layer 3 (40-wide, OUTP=48) + fused log_softmax ----
    gemmw_kernel<OUT_C, 48><<<nb_W, T>>>(
        reinterpret_cast<const __half*>(p_hh), W2, p_msg, N);
    aggregateh_kernel<OUT_C / 4, 1><<<nb_A, T>>>(p_msg, b2, out, N);
}

// round 16
// speedup vs baseline: 1.4332x; 1.0667x over previous
#include <cuda_runtime.h>
#include <cuda_fp16.h>
#include <mma.h>
#include <math.h>

using namespace nvcuda;

#define N_NODES 100000
#define N_EDGES 1600000
#define IN_C 64
#define HID_C 64
#define OUT_C 40
#define SCAN_BS 512
#define SCAN_NB ((N_NODES + SCAN_BS - 1) / SCAN_BS)   // 196

// Scratch (allocation-free rule: __device__ globals)
__device__ uint2 g_msg[(size_t)N_NODES * (HID_C / 4)]; // fp16 pre-scaled messages (dinv[src]*y)
__device__ uint2 g_hh[(size_t)N_NODES * (HID_C / 4)];  // fp16 relu(h) (gemm input)
__device__ uint2 g_xh[(size_t)N_NODES * (IN_C / 4)];   // fp16 copy of x
__device__ float g_dinv[N_NODES];
__device__ int   g_deg[N_NODES];
__device__ int   g_rowptr[N_NODES + 1];
__device__ int   g_cursor[N_NODES];
__device__ int   g_bsum[SCAN_NB];
__device__ int   g_esrc[N_EDGES];                  // src index only, binned by dst

// ---------------------------------------------------------------------------
// fp16 pack helpers
// ---------------------------------------------------------------------------
__device__ __forceinline__ float4 h4_to_f4(uint2 raw) {
    __half2 a = *reinterpret_cast<__half2*>(&raw.x);
    __half2 b = *reinterpret_cast<__half2*>(&raw.y);
    float2 fa = __half22float2(a);
    float2 fb = __half22float2(b);
    return make_float4(fa.x, fa.y, fb.x, fb.y);
}
__device__ __forceinline__ uint2 f4_to_h4(float4 v) {
    __half2 a = __floats2half2_rn(v.x, v.y);
    __half2 b = __floats2half2_rn(v.z, v.w);
    uint2 o;
    o.x = *reinterpret_cast<unsigned int*>(&a);
    o.y = *reinterpret_cast<unsigned int*>(&b);
    return o;
}

// ---------------------------------------------------------------------------
// x -> fp16 (independent of everything; runs on s2 at t=0)
// ---------------------------------------------------------------------------
__global__ void x2h_kernel(const float4* __restrict__ x4, uint2* __restrict__ xh, int n4) {
    int i = blockIdx.x * blockDim.x + threadIdx.x;
    if (i < n4) xh[i] = f4_to_h4(x4[i]);
}

// ---------------------------------------------------------------------------
// degree
// ---------------------------------------------------------------------------
__global__ void deg_kernel(const int* __restrict__ dst, int E) {
    int i = blockIdx.x * blockDim.x + threadIdx.x;
    if (i < E) atomicAdd(&g_deg[dst[i]], 1);
}

// ---------------------------------------------------------------------------
// CSR build: block-wise exclusive scan of deg -> rowptr (dinv fused here)
// ---------------------------------------------------------------------------
__global__ void scan_block_kernel(int N) {
    __shared__ int s[SCAN_BS];
    int i = blockIdx.x * SCAN_BS + threadIdx.x;
    int v = (i < N) ? g_deg[i] : 0;
    if (i < N) g_dinv[i] = rsqrtf((float)(v + 1));     // +1 self loop; always > 0
    s[threadIdx.x] = v;
    __syncthreads();
#pragma unroll
    for (int off = 1; off < SCAN_BS; off <<= 1) {
        int t = 0;
        if (threadIdx.x >= off) t = s[threadIdx.x - off];
        __syncthreads();
        if (threadIdx.x >= off) s[threadIdx.x] += t;
        __syncthreads();
    }
    if (i < N) g_rowptr[i] = s[threadIdx.x] - v;       // exclusive, block-local
    if (threadIdx.x == SCAN_BS - 1) g_bsum[blockIdx.x] = s[SCAN_BS - 1];
}

// add block offsets (each block redundantly scans the 196 block sums in smem)
__global__ void add_off_kernel(int N, int E) {
    __shared__ int s[256];
    int t = threadIdx.x;
    int v = (t < SCAN_NB) ? g_bsum[t] : 0;
    s[t] = v;
    __syncthreads();
#pragma unroll
    for (int off = 1; off < 256; off <<= 1) {
        int u = 0;
        if (t >= off) u = s[t - off];
        __syncthreads();
        if (t >= off) s[t] += u;
        __syncthreads();
    }
    int i = blockIdx.x * blockDim.x + threadIdx.x;
    if (i < N) {
        int b = i >> 9;
        int off = (b > 0) ? s[b - 1] : 0;          // exclusive prefix of bsum
        int r = g_rowptr[i] + off;
        g_rowptr[i] = r;
        g_cursor[i] = r;
    }
    if (i == 0) g_rowptr[N] = E;
}

// bin edges by dst; store src index only (norm is factored out)
__global__ void fill_kernel(const int* __restrict__ src, const int* __restrict__ dst, int E) {
    int e = blockIdx.x * blockDim.x + threadIdx.x;
    if (e >= E) return;
    int d = dst[e];
    int pos = atomicAdd(&g_cursor[d], 1);
    g_esrc[pos] = src[e];
}

// ---------------------------------------------------------------------------
// wmma GEMM v2: msg'[r,:] = dinv[r] * (Xh[r,:] @ W)
// A staged in smem (coalesced uint4 loads, padded ld=72); per-n-tile C pack
// through a small per-warp buffer. Block = 8 warps x 16 rows.
// ---------------------------------------------------------------------------
template <int OUT, int OUTP>
__global__ void __launch_bounds__(256) gemmw_kernel(const __half* __restrict__ Xh,
                                                    const float* __restrict__ W,
                                                    uint2* __restrict__ Yh, int N) {
    constexpr int NT = OUTP / 16;     // n tiles per warp (4 or 3)
    constexpr int C4 = OUT / 4;       // uint2 per output row
    __shared__ __half Ws[64 * OUTP];
    __shared__ __half As[128 * 72];   // A tile, padded (144 B rows)
    __shared__ float  Cs[8][16 * 20]; // per-warp n-tile staging (ld=20)

    int tid = threadIdx.x;
    for (int i = tid; i < 64 * OUTP; i += 256) {
        int k = i / OUTP, n = i % OUTP;
        Ws[i] = (n < OUT) ? __float2half(W[k * OUT + n]) : __half(0.f);
    }
    int row0blk = blockIdx.x * 128;
    {
        // cooperative A load: 128 rows x 64 halves = 1024 uint4, 4 per thread
        const uint4* srcp = reinterpret_cast<const uint4*>(Xh + (size_t)row0blk * 64);
        for (int i = tid; i < 128 * 8; i += 256) {
            int r = i >> 3, c = i & 7;
            uint4 v = make_uint4(0u, 0u, 0u, 0u);
            if (row0blk + r < N) v = srcp[r * 8 + c];
            *reinterpret_cast<uint4*>(&As[r * 72 + c * 8]) = v;
        }
    }
    __syncthreads();

    int warp = tid >> 5;
    int lane = tid & 31;
    int row0 = row0blk + warp * 16;
    if (row0 >= N) return;   // N % 16 == 0: warp tiles never straddle N

    wmma::fragment<wmma::matrix_a, 16, 16, 16, __half, wmma::row_major> a;
    wmma::fragment<wmma::matrix_b, 16, 16, 16, __half, wmma::row_major> b;
    wmma::fragment<wmma::accumulator, 16, 16, 16, float> c[NT];
#pragma unroll
    for (int n = 0; n < NT; n++) wmma::fill_fragment(c[n], 0.f);

#pragma unroll
    for (int k = 0; k < 4; k++) {
        wmma::load_matrix_sync(a, As + (warp * 16) * 72 + k * 16, 72);
#pragma unroll
        for (int n = 0; n < NT; n++) {
            wmma::load_matrix_sync(b, Ws + (k * 16) * OUTP + n * 16, OUTP);
            wmma::mma_sync(c[n], a, b, c[n]);
        }
    }

    // per-n-tile pack: lane -> (row = lane/2, half-row = lane&1 -> 8 cols)
    float* cw = Cs[warp];
    int r = lane >> 1, halfc = lane & 1;
    int grow = row0 + r;
    float di = g_dinv[grow];
    uint2* yrow = Yh + (size_t)grow * C4;
#pragma unroll
    for (int n = 0; n < NT; n++) {
        wmma::store_matrix_sync(cw, c[n], 20, wmma::mem_row_major);
        __syncwarp();
        const float* cr = cw + r * 20 + halfc * 8;
#pragma unroll
        for (int j = 0; j < 2; j++) {
            int idx = n * 4 + halfc * 2 + j;
            if (idx < C4) {
                float4 v = *reinterpret_cast<const float4*>(cr + 4 * j);
                yrow[idx] = f4_to_h4(make_float4(di * v.x, di * v.y, di * v.z, di * v.w));
            }
        }
        __syncwarp();
    }
}

// ---------------------------------------------------------------------------
// CSR aggregate over pre-scaled fp16 messages (round-9 proven loop structure):
//   sum = msg'[row] + Sum_e msg'[src_e];  res = b + dinv[row] * sum
// MODE 0: write fp16 relu(res) (gemm input). MODE 1: fused log_softmax, fp32.
// ---------------------------------------------------------------------------
template <int C4, int MODE>
__global__ void aggregateh_kernel(const uint2* __restrict__ th, const float* __restrict__ b,
                                  void* __restrict__ outp, int N) {
    int g    = blockIdx.x * 16 + (threadIdx.x >> 4);
    int lane = threadIdx.x & 15;
    bool rowok = (g < N);
    int row  = rowok ? g : 0;
    bool act = rowok && (lane < C4);

    const float4* b4 = reinterpret_cast<const float4*>(b);

    float4 acc = make_float4(0.f, 0.f, 0.f, 0.f);
    int beg = 0, end = 0;
    if (rowok) {
        beg = g_rowptr[row];
        end = g_rowptr[row + 1];
    }
    if (act)   // self-loop message
        acc = h4_to_f4(__ldg(&th[(size_t)row * C4 + lane]));

    int j = beg;
    for (; j + 3 < end; j += 4) {                       // 4-way unroll for MLP
        int s0 = __ldg(&g_esrc[j]);
        int s1 = __ldg(&g_esrc[j + 1]);
        int s2 = __ldg(&g_esrc[j + 2]);
        int s3 = __ldg(&g_esrc[j + 3]);
        if (act) {
            float4 v0 = h4_to_f4(__ldg(&th[(size_t)s0 * C4 + lane]));
            float4 v1 = h4_to_f4(__ldg(&th[(size_t)s1 * C4 + lane]));
            float4 v2 = h4_to_f4(__ldg(&th[(size_t)s2 * C4 + lane]));
            float4 v3 = h4_to_f4(__ldg(&th[(size_t)s3 * C4 + lane]));
            acc.x += (v0.x + v1.x) + (v2.x + v3.x);
            acc.y += (v0.y + v1.y) + (v2.y + v3.y);
            acc.z += (v0.z + v1.z) + (v2.z + v3.z);
            acc.w += (v0.w + v1.w) + (v2.w + v3.w);
        }
    }
    for (; j < end; j++) {
        int s0 = __ldg(&g_esrc[j]);
        if (act) {
            float4 v0 = h4_to_f4(__ldg(&th[(size_t)s0 * C4 + lane]));
            acc.x += v0.x; acc.y += v0.y;
            acc.z += v0.z; acc.w += v0.w;
        }
    }

    float4 res = make_float4(0.f, 0.f, 0.f, 0.f);
    if (act) {
        float di = g_dinv[row];
        float4 bb = b4[lane];
        res.x = bb.x + di * acc.x; res.y = bb.y + di * acc.y;
        res.z = bb.z + di * acc.z; res.w = bb.w + di * acc.w;
    }

    if (MODE == 0) {
        if (act) {
            // relu folded here (next gemm consumes pure A@W input)
            res.x = fmaxf(res.x, 0.f); res.y = fmaxf(res.y, 0.f);
            res.z = fmaxf(res.z, 0.f); res.w = fmaxf(res.w, 0.f);
            reinterpret_cast<uint2*>(outp)[(size_t)row * C4 + lane] = f4_to_h4(res);
        }
    } else {
        // row-wise log_softmax across the 16-lane group (width-16 butterfly)
        float m = act ? fmaxf(fmaxf(res.x, res.y), fmaxf(res.z, res.w)) : -INFINITY;
#pragma unroll
        for (int k = 8; k >= 1; k >>= 1)
            m = fmaxf(m, __shfl_xor_sync(0xffffffffu, m, k, 16));
        float s = act ? (__expf(res.x - m) + __expf(res.y - m) +
                         __expf(res.z - m) + __expf(res.w - m)) : 0.f;
#pragma unroll
        for (int k = 8; k >= 1; k >>= 1)
            s += __shfl_xor_sync(0xffffffffu, s, k, 16);
        float l = m + logf(s);
        if (act) {
            reinterpret_cast<float4*>(outp)[(size_t)row * C4 + lane] =
                make_float4(res.x - l, res.y - l, res.z - l, res.w - l);
        }
    }
}

// ---------------------------------------------------------------------------
// launcher
// ---------------------------------------------------------------------------
extern "C" void kernel_launch(void* const* d_in, const int* in_sizes, int n_in,
                              void* d_out, int out_size) {
    const float* x  = (const float*)d_in[0];
    const int*   ei = (const int*)d_in[1];
    const float* W1 = (const float*)d_in[2];
    const float* b1 = (const float*)d_in[3];
    const float* Wh = (const float*)d_in[4];
    const float* bh = (const float*)d_in[5];
    const float* W2 = (const float*)d_in[6];
    const float* b2 = (const float*)d_in[7];
    float* out = (float*)d_out;

    int N = in_sizes[0] / IN_C;
    int E = in_sizes[1] / 2;
    const int* src = ei;
    const int* dst = ei + E;

    uint2 *p_msg, *p_hh, *p_xh;
    int* p_deg;
    cudaGetSymbolAddress((void**)&p_msg, g_msg);
    cudaGetSymbolAddress((void**)&p_hh, g_hh);
    cudaGetSymbolAddress((void**)&p_xh, g_xh);
    cudaGetSymbolAddress((void**)&p_deg, g_deg);

    static cudaStream_t s2 = nullptr;
    static cudaEvent_t evDinv = nullptr, evJoin = nullptr;
    if (!s2) {
        cudaStreamCreateWithFlags(&s2, cudaStreamNonBlocking);
        cudaEventCreateWithFlags(&evDinv, cudaEventDisableTiming);
        cudaEventCreateWithFlags(&evJoin, cudaEventDisableTiming);
    }

    const int T = 256;
    int nb_N = (N + T - 1) / T;
    int nb_E = (E + T - 1) / T;
    int nb_W = (N + 127) / 128;   // wmma gemm: 128 rows/block
    int nb_A = (N + 15) / 16;     // aggregate: 16 rows/block
    int n4   = N * (IN_C / 4);

    // ---- dinv chain on default stream ----
    cudaMemsetAsync(p_deg, 0, (size_t)N * sizeof(int), 0);
    deg_kernel<<<nb_E, T>>>(dst, E);
    scan_block_kernel<<<SCAN_NB, SCAN_BS>>>(N);   // computes dinv + block sums
    cudaEventRecord(evDinv, 0);

    // ---- s2: x->fp16 at t=0, then layer-1 wmma GEMM (needs dinv) ----
    x2h_kernel<<<(n4 + T - 1) / T, T, 0, s2>>>(
        reinterpret_cast<const float4*>(x), p_xh, n4);
    cudaStreamWaitEvent(s2, evDinv, 0);
    gemmw_kernel<HID_C, 64><<<nb_W, T, 0, s2>>>(
        reinterpret_cast<const __half*>(p_xh), W1, p_msg, N);
    cudaEventRecord(evJoin, s2);

    // ---- rest of CSR build on default stream (overlaps gemm1) ----
    add_off_kernel<<<nb_N, T>>>(N, E);            // folds block-sum prefix in
    fill_kernel<<<nb_E, T>>>(src, dst, E);

    // ---- layer 1: aggregate -> fp16 relu(h) ----
    cudaStreamWaitEvent(0, evJoin, 0);
    aggregateh_kernel<HID_C / 4, 0><<<nb_A, T>>>(p_msg, b1, p_hh, N);

    // ---- layer 2 ----
    gemmw_kernel<HID_C, 64><<<nb_W, T>>>(
        reinterpret_cast<const __half*>(p_hh), Wh, p_msg, N);
    aggregateh_kernel<HID_C / 4, 0><<<nb_A, T>>>(p_msg, bh, p_hh, N);

    // ---- layer 3 (40-wide, OUTP=48) + fused log_softmax ----
    gemmw_kernel<OUT_C, 48><<<nb_W, T>>>(
        reinterpret_cast<const __half*>(p_hh), W2, p_msg, N);
    aggregateh_kernel<OUT_C / 4, 1><<<nb_A, T>>>(p_msg, b2, out, N);
}

// round 17
// speedup vs baseline: 1.4863x; 1.0370x over previous
#include <cuda_runtime.h>
#include <cuda_fp16.h>
#include <mma.h>
#include <math.h>

using namespace nvcuda;

#define N_NODES 100000
#define N_EDGES 1600000
#define IN_C 64
#define HID_C 64
#define OUT_C 40
#define SCAN_BS 512
#define SCAN_NB ((N_NODES + SCAN_BS - 1) / SCAN_BS)   // 196

// Scratch (allocation-free rule: __device__ globals)
__device__ uint2 g_msg[(size_t)N_NODES * (HID_C / 4)]; // fp16 pre-scaled messages (dinv[src]*y)
__device__ uint2 g_hh[(size_t)N_NODES * (HID_C / 4)];  // fp16 relu(h) (gemm input)
__device__ uint2 g_xh[(size_t)N_NODES * (IN_C / 4)];   // fp16 copy of x
__device__ __half g_w1h[64 * 64];                      // fp16 W1
__device__ __half g_whh[64 * 64];                      // fp16 Wh
__device__ __half g_w2h[64 * 48];                      // fp16 W2 (40->48 zero-pad)
__device__ float g_dinv[N_NODES];
__device__ int   g_deg[N_NODES];
__device__ int   g_rowptr[N_NODES + 1];
__device__ int   g_cursor[N_NODES];
__device__ int   g_bsum[SCAN_NB];
__device__ int   g_esrc[N_EDGES];                  // src index only, binned by dst

// ---------------------------------------------------------------------------
// fp16 pack helpers
// ---------------------------------------------------------------------------
__device__ __forceinline__ float4 h4_to_f4(uint2 raw) {
    __half2 a = *reinterpret_cast<__half2*>(&raw.x);
    __half2 b = *reinterpret_cast<__half2*>(&raw.y);
    float2 fa = __half22float2(a);
    float2 fb = __half22float2(b);
    return make_float4(fa.x, fa.y, fb.x, fb.y);
}
__device__ __forceinline__ uint2 f4_to_h4(float4 v) {
    __half2 a = __floats2half2_rn(v.x, v.y);
    __half2 b = __floats2half2_rn(v.z, v.w);
    uint2 o;
    o.x = *reinterpret_cast<unsigned int*>(&a);
    o.y = *reinterpret_cast<unsigned int*>(&b);
    return o;
}

// ---------------------------------------------------------------------------
// one-shot conversions (run on s2 at t=0, no dependencies)
// ---------------------------------------------------------------------------
__global__ void x2h_kernel(const float4* __restrict__ x4, uint2* __restrict__ xh, int n4) {
    int i = blockIdx.x * blockDim.x + threadIdx.x;
    if (i < n4) xh[i] = f4_to_h4(x4[i]);
}

__global__ void w2h_kernel(const float* __restrict__ W1, const float* __restrict__ Wh,
                           const float* __restrict__ W2) {
    int i = blockIdx.x * blockDim.x + threadIdx.x;
    if (i < 64 * 64) g_w1h[i] = __float2half(W1[i]);
    if (i < 64 * 64) g_whh[i] = __float2half(Wh[i]);
    if (i < 64 * 48) {
        int k = i / 48, n = i % 48;
        g_w2h[i] = (n < OUT_C) ? __float2half(W2[k * OUT_C + n]) : __half(0.f);
    }
}

// ---------------------------------------------------------------------------
// degree
// ---------------------------------------------------------------------------
__global__ void deg_kernel(const int* __restrict__ dst, int E) {
    int i = blockIdx.x * blockDim.x + threadIdx.x;
    if (i < E) atomicAdd(&g_deg[dst[i]], 1);
}

// ---------------------------------------------------------------------------
// CSR build: block-wise exclusive scan of deg -> rowptr (dinv fused here)
// ---------------------------------------------------------------------------
__global__ void scan_block_kernel(int N) {
    __shared__ int s[SCAN_BS];
    int i = blockIdx.x * SCAN_BS + threadIdx.x;
    int v = (i < N) ? g_deg[i] : 0;
    if (i < N) g_dinv[i] = rsqrtf((float)(v + 1));     // +1 self loop; always > 0
    s[threadIdx.x] = v;
    __syncthreads();
#pragma unroll
    for (int off = 1; off < SCAN_BS; off <<= 1) {
        int t = 0;
        if (threadIdx.x >= off) t = s[threadIdx.x - off];
        __syncthreads();
        if (threadIdx.x >= off) s[threadIdx.x] += t;
        __syncthreads();
    }
    if (i < N) g_rowptr[i] = s[threadIdx.x] - v;       // exclusive, block-local
    if (threadIdx.x == SCAN_BS - 1) g_bsum[blockIdx.x] = s[SCAN_BS - 1];
}

// add block offsets (each block redundantly scans the 196 block sums in smem)
__global__ void add_off_kernel(int N, int E) {
    __shared__ int s[256];
    int t = threadIdx.x;
    int v = (t < SCAN_NB) ? g_bsum[t] : 0;
    s[t] = v;
    __syncthreads();
#pragma unroll
    for (int off = 1; off < 256; off <<= 1) {
        int u = 0;
        if (t >= off) u = s[t - off];
        __syncthreads();
        if (t >= off) s[t] += u;
        __syncthreads();
    }
    int i = blockIdx.x * blockDim.x + threadIdx.x;
    if (i < N) {
        int b = i >> 9;
        int off = (b > 0) ? s[b - 1] : 0;          // exclusive prefix of bsum
        int r = g_rowptr[i] + off;
        g_rowptr[i] = r;
        g_cursor[i] = r;
    }
    if (i == 0) g_rowptr[N] = E;
}

// bin edges by dst; store src index only (norm is factored out)
__global__ void fill_kernel(const int* __restrict__ src, const int* __restrict__ dst, int E) {
    int e = blockIdx.x * blockDim.x + threadIdx.x;
    if (e >= E) return;
    int d = dst[e];
    int pos = atomicAdd(&g_cursor[d], 1);
    g_esrc[pos] = src[e];
}

// ---------------------------------------------------------------------------
// wmma GEMM v3: msg'[r,:] = dinv[r] * (Xh[r,:] @ W)
// W pre-converted fp16 (coalesced uint4 staging); A staged in smem; a-frags
// hoisted (loaded once); n-outer/k-inner mma loop. Block = 8 warps x 16 rows.
// ---------------------------------------------------------------------------
template <int OUT, int OUTP>
__global__ void __launch_bounds__(256) gemmw_kernel(const __half* __restrict__ Xh,
                                                    const __half* __restrict__ Wh_,
                                                    uint2* __restrict__ Yh, int N) {
    constexpr int NT = OUTP / 16;     // n tiles per warp (4 or 3)
    constexpr int C4 = OUT / 4;       // uint2 per output row
    __shared__ __half Ws[64 * OUTP];
    __shared__ __half As[128 * 72];   // A tile, padded (144 B rows)
    __shared__ float  Cs[8][16 * 20]; // per-warp n-tile staging (ld=20)

    int tid = threadIdx.x;
    {
        // W staging: 64*OUTP halves = OUTP*8 uint4, coalesced
        const uint4* wsrc = reinterpret_cast<const uint4*>(Wh_);
        uint4* wdst = reinterpret_cast<uint4*>(Ws);
        for (int i = tid; i < 8 * OUTP; i += 256) wdst[i] = wsrc[i];
    }
    int row0blk = blockIdx.x * 128;
    {
        // cooperative A load: 128 rows x 64 halves = 1024 uint4, 4 per thread
        const uint4* srcp = reinterpret_cast<const uint4*>(Xh + (size_t)row0blk * 64);
        for (int i = tid; i < 128 * 8; i += 256) {
            int r = i >> 3, c = i & 7;
            uint4 v = make_uint4(0u, 0u, 0u, 0u);
            if (row0blk + r < N) v = srcp[r * 8 + c];
            *reinterpret_cast<uint4*>(&As[r * 72 + c * 8]) = v;
        }
    }
    __syncthreads();

    int warp = tid >> 5;
    int lane = tid & 31;
    int row0 = row0blk + warp * 16;
    if (row0 >= N) return;   // N % 16 == 0: warp tiles never straddle N

    wmma::fragment<wmma::matrix_a, 16, 16, 16, __half, wmma::row_major> a[4];
#pragma unroll
    for (int k = 0; k < 4; k++)
        wmma::load_matrix_sync(a[k], As + (warp * 16) * 72 + k * 16, 72);

    wmma::fragment<wmma::accumulator, 16, 16, 16, float> c[NT];
#pragma unroll
    for (int n = 0; n < NT; n++) wmma::fill_fragment(c[n], 0.f);

#pragma unroll
    for (int n = 0; n < NT; n++) {
#pragma unroll
        for (int k = 0; k < 4; k++) {
            wmma::fragment<wmma::matrix_b, 16, 16, 16, __half, wmma::row_major> b;
            wmma::load_matrix_sync(b, Ws + (k * 16) * OUTP + n * 16, OUTP);
            wmma::mma_sync(c[n], a[k], b, c[n]);
        }
    }

    // per-n-tile pack: lane -> (row = lane/2, half-row = lane&1 -> 8 cols)
    float* cw = Cs[warp];
    int r = lane >> 1, halfc = lane & 1;
    int grow = row0 + r;
    float di = g_dinv[grow];
    uint2* yrow = Yh + (size_t)grow * C4;
#pragma unroll
    for (int n = 0; n < NT; n++) {
        wmma::store_matrix_sync(cw, c[n], 20, wmma::mem_row_major);
        __syncwarp();
        const float* cr = cw + r * 20 + halfc * 8;
#pragma unroll
        for (int j = 0; j < 2; j++) {
            int idx = n * 4 + halfc * 2 + j;
            if (idx < C4) {
                float4 v = *reinterpret_cast<const float4*>(cr + 4 * j);
                yrow[idx] = f4_to_h4(make_float4(di * v.x, di * v.y, di * v.z, di * v.w));
            }
        }
        __syncwarp();
    }
}

// ---------------------------------------------------------------------------
// CSR aggregate over pre-scaled fp16 messages (round-9 proven loop structure):
//   sum = msg'[row] + Sum_e msg'[src_e];  res = b + dinv[row] * sum
// MODE 0: write fp16 relu(res) (gemm input). MODE 1: fused log_softmax, fp32.
// ---------------------------------------------------------------------------
template <int C4, int MODE>
__global__ void aggregateh_kernel(const uint2* __restrict__ th, const float* __restrict__ b,
                                  void* __restrict__ outp, int N) {
    int g    = blockIdx.x * 16 + (threadIdx.x >> 4);
    int lane = threadIdx.x & 15;
    bool rowok = (g < N);
    int row  = rowok ? g : 0;
    bool act = rowok && (lane < C4);

    const float4* b4 = reinterpret_cast<const float4*>(b);

    float4 acc = make_float4(0.f, 0.f, 0.f, 0.f);
    int beg = 0, end = 0;
    if (rowok) {
        beg = g_rowptr[row];
        end = g_rowptr[row + 1];
    }
    if (act)   // self-loop message
        acc = h4_to_f4(__ldg(&th[(size_t)row * C4 + lane]));

    int j = beg;
    for (; j + 3 < end; j += 4) {                       // 4-way unroll for MLP
        int s0 = __ldg(&g_esrc[j]);
        int s1 = __ldg(&g_esrc[j + 1]);
        int s2 = __ldg(&g_esrc[j + 2]);
        int s3 = __ldg(&g_esrc[j + 3]);
        if (act) {
            float4 v0 = h4_to_f4(__ldg(&th[(size_t)s0 * C4 + lane]));
            float4 v1 = h4_to_f4(__ldg(&th[(size_t)s1 * C4 + lane]));
            float4 v2 = h4_to_f4(__ldg(&th[(size_t)s2 * C4 + lane]));
            float4 v3 = h4_to_f4(__ldg(&th[(size_t)s3 * C4 + lane]));
            acc.x += (v0.x + v1.x) + (v2.x + v3.x);
            acc.y += (v0.y + v1.y) + (v2.y + v3.y);
            acc.z += (v0.z + v1.z) + (v2.z + v3.z);
            acc.w += (v0.w + v1.w) + (v2.w + v3.w);
        }
    }
    for (; j < end; j++) {
        int s0 = __ldg(&g_esrc[j]);
        if (act) {
            float4 v0 = h4_to_f4(__ldg(&th[(size_t)s0 * C4 + lane]));
            acc.x += v0.x; acc.y += v0.y;
            acc.z += v0.z; acc.w += v0.w;
        }
    }

    float4 res = make_float4(0.f, 0.f, 0.f, 0.f);
    if (act) {
        float di = g_dinv[row];
        float4 bb = b4[lane];
        res.x = bb.x + di * acc.x; res.y = bb.y + di * acc.y;
        res.z = bb.z + di * acc.z; res.w = bb.w + di * acc.w;
    }

    if (MODE == 0) {
        if (act) {
            // relu folded here (next gemm consumes pure A@W input)
            res.x = fmaxf(res.x, 0.f); res.y = fmaxf(res.y, 0.f);
            res.z = fmaxf(res.z, 0.f); res.w = fmaxf(res.w, 0.f);
            reinterpret_cast<uint2*>(outp)[(size_t)row * C4 + lane] = f4_to_h4(res);
        }
    } else {
        // row-wise log_softmax across the 16-lane group (width-16 butterfly)
        float m = act ? fmaxf(fmaxf(res.x, res.y), fmaxf(res.z, res.w)) : -INFINITY;
#pragma unroll
        for (int k = 8; k >= 1; k >>= 1)
            m = fmaxf(m, __shfl_xor_sync(0xffffffffu, m, k, 16));
        float s = act ? (__expf(res.x - m) + __expf(res.y - m) +
                         __expf(res.z - m) + __expf(res.w - m)) : 0.f;
#pragma unroll
        for (int k = 8; k >= 1; k >>= 1)
            s += __shfl_xor_sync(0xffffffffu, s, k, 16);
        float l = m + logf(s);
        if (act) {
            reinterpret_cast<float4*>(outp)[(size_t)row * C4 + lane] =
                make_float4(res.x - l, res.y - l, res.z - l, res.w - l);
        }
    }
}

// ---------------------------------------------------------------------------
// launcher
// ---------------------------------------------------------------------------
extern "C" void kernel_launch(void* const* d_in, const int* in_sizes, int n_in,
                              void* d_out, int out_size) {
    const float* x  = (const float*)d_in[0];
    const int*   ei = (const int*)d_in[1];
    const float* W1 = (const float*)d_in[2];
    const float* b1 = (const float*)d_in[3];
    const float* Wh = (const float*)d_in[4];
    const float* bh = (const float*)d_in[5];
    const float* W2 = (const float*)d_in[6];
    const float* b2 = (const float*)d_in[7];
    float* out = (float*)d_out;

    int N = in_sizes[0] / IN_C;
    int E = in_sizes[1] / 2;
    const int* src = ei;
    const int* dst = ei + E;

    uint2 *p_msg, *p_hh, *p_xh;
    __half *p_w1h, *p_whh, *p_w2h;
    int* p_deg;
    cudaGetSymbolAddress((void**)&p_msg, g_msg);
    cudaGetSymbolAddress((void**)&p_hh, g_hh);
    cudaGetSymbolAddress((void**)&p_xh, g_xh);
    cudaGetSymbolAddress((void**)&p_w1h, g_w1h);
    cudaGetSymbolAddress((void**)&p_whh, g_whh);
    cudaGetSymbolAddress((void**)&p_w2h, g_w2h);
    cudaGetSymbolAddress((void**)&p_deg, g_deg);

    static cudaStream_t s2 = nullptr;
    static cudaEvent_t evDinv = nullptr, evJoin = nullptr;
    if (!s2) {
        cudaStreamCreateWithFlags(&s2, cudaStreamNonBlocking);
        cudaEventCreateWithFlags(&evDinv, cudaEventDisableTiming);
        cudaEventCreateWithFlags(&evJoin, cudaEventDisableTiming);
    }

    const int T = 256;
    int nb_N = (N + T - 1) / T;
    int nb_E = (E + T - 1) / T;
    int nb_W = (N + 127) / 128;   // wmma gemm: 128 rows/block
    int nb_A = (N + 15) / 16;     // aggregate: 16 rows/block
    int n4   = N * (IN_C / 4);

    // ---- dinv chain on default stream ----
    cudaMemsetAsync(p_deg, 0, (size_t)N * sizeof(int), 0);
    deg_kernel<<<nb_E, T>>>(dst, E);
    scan_block_kernel<<<SCAN_NB, SCAN_BS>>>(N);   // computes dinv + block sums
    cudaEventRecord(evDinv, 0);

    // ---- s2: x->fp16 and W->fp16 at t=0, then layer-1 wmma GEMM ----
    x2h_kernel<<<(n4 + T - 1) / T, T, 0, s2>>>(
        reinterpret_cast<const float4*>(x), p_xh, n4);
    w2h_kernel<<<16, T, 0, s2>>>(W1, Wh, W2);
    cudaStreamWaitEvent(s2, evDinv, 0);
    gemmw_kernel<HID_C, 64><<<nb_W, T, 0, s2>>>(
        reinterpret_cast<const __half*>(p_xh), p_w1h, p_msg, N);
    cudaEventRecord(evJoin, s2);

    // ---- rest of CSR build on default stream (overlaps gemm1) ----
    add_off_kernel<<<nb_N, T>>>(N, E);            // folds block-sum prefix in
    fill_kernel<<<nb_E, T>>>(src, dst, E);

    // ---- layer 1: aggregate -> fp16 relu(h) ----
    cudaStreamWaitEvent(0, evJoin, 0);
    aggregateh_kernel<HID_C / 4, 0><<<nb_A, T>>>(p_msg, b1, p_hh, N);

    // ---- layer 2 ----
    gemmw_kernel<HID_C, 64><<<nb_W, T>>>(
        reinterpret_cast<const __half*>(p_hh), p_whh, p_msg, N);
    aggregateh_kernel<HID_C / 4, 0><<<nb_A, T>>>(p_msg, bh, p_hh, N);

    // ---- layer 3 (40-wide, OUTP=48) + fused log_softmax ----
    gemmw_kernel<OUT_C, 48><<<nb_W, T>>>(
        reinterpret_cast<const __half*>(p_hh), p_w2h, p_msg, N);
    aggregateh_kernel<OUT_C / 4, 1><<<nb_A, T>>>(p_msg, b2, out, N);
}